// round 11
// baseline (speedup 1.0000x reference)
#include <cuda_runtime.h>
#include <cuda_bf16.h>
#include <math.h>

#define B_  32
#define T_  512
#define D_  1024
#define UN_ 1024
#define NG_ 3072
#define M_  (B_*T_)
#define NBLK 128

typedef unsigned long long ull;
typedef unsigned int u32;

// ---------------- packed f32x2 helpers ----------------
#define FMA2(d, a, b) asm("fma.rn.f32x2 %0, %1, %2, %0;" : "+l"(d) : "l"(a), "l"(b))
#define ADD2(d, v)    asm("add.rn.f32x2 %0, %0, %1;"     : "+l"(d) : "l"(v))
#define DUP2(d, s)    asm("mov.b64 %0, {%1, %1};"        : "=l"(d) : "r"(s))

union F2U { ull u; float f[2]; };

// ---------------- cp.async helpers ----------------
__device__ __forceinline__ unsigned sptr(const void* p) {
    return (unsigned)__cvta_generic_to_shared(p);
}
#define CPA16(s, g)  asm volatile("cp.async.cg.shared.global [%0], [%1], 16;" :: "r"(s), "l"(g))
#define CPCOMMIT()   asm volatile("cp.async.commit_group;")
#define CPWAIT1()    asm volatile("cp.async.wait_group 1;")
#define CPWAIT0()    asm volatile("cp.async.wait_group 0;")

// ---------------- bf16 helpers ----------------
__device__ __forceinline__ unsigned short bfu(float v) {
    __nv_bfloat16 b = __float2bfloat16(v);
    return *(unsigned short*)&b;
}
__device__ __forceinline__ float ubf(unsigned short u) {
    return __bfloat162float(*(__nv_bfloat16*)&u);
}

// ---------------- mma.sync bf16 ----------------
#define MMA16816(c, a, b0, b1)                                              \
    asm("mma.sync.aligned.m16n8k16.row.col.f32.bf16.bf16.f32 "              \
        "{%0,%1,%2,%3}, {%4,%5,%6,%7}, {%8,%9}, {%0,%1,%2,%3};"             \
        : "+f"((c)[0]), "+f"((c)[1]), "+f"((c)[2]), "+f"((c)[3])            \
        : "r"((a)[0]), "r"((a)[1]), "r"((a)[2]), "r"((a)[3]),               \
          "r"(b0), "r"(b1))

// ---------------- device scratch ----------------
__device__ __align__(16) float g_xp[(size_t)M_ * NG_];        // [row][col]
__device__ __align__(16) float g_xpt[(size_t)T_ * NG_ * B_];  // [t][col][b], bias folded
__device__ __align__(16) float g_bsum[NG_];
__device__ __align__(16) float g_hT[2][UN_ * B_];             // [u][b]
__device__ __align__(16) float g_rhT[2][UN_ * B_];            // [u][b], parity t&1
__device__ __align__(128) unsigned g_rc[8 * 32];              // rh chunk counters (line-padded)
__device__ __align__(128) unsigned g_hc[8 * 32];              // h  chunk counters
// bf16 split operands
__device__ __align__(16) __nv_bfloat16 g_xh[(size_t)M_ * D_];
__device__ __align__(16) __nv_bfloat16 g_xl[(size_t)M_ * D_];
__device__ __align__(16) __nv_bfloat16 g_Wht[(size_t)NG_ * D_];  // [n][k]
__device__ __align__(16) __nv_bfloat16 g_Wlt[(size_t)NG_ * D_];  // [n][k]

#define POLLGE(p, tgt) while (*((volatile unsigned*)(p)) < (tgt)) { }

// ---------------- bias column sums ----------------
__global__ void k_bsum(const float* __restrict__ b) {
    int c = blockIdx.x * 256 + threadIdx.x;
    float acc = 0.f;
    for (int k = 0; k < D_; k++) acc += b[(size_t)k * NG_ + c];
    g_bsum[c] = acc;
}

// ---------------- init ----------------
__global__ void k_init(const float* __restrict__ h0) {
    int i = blockIdx.x * 256 + threadIdx.x;
    if (i < B_ * UN_) {
        int u = i >> 5, b = i & 31;
        g_hT[0][i] = h0[b * UN_ + u];
    }
    if (blockIdx.x == 0 && threadIdx.x < 8) {
        g_rc[threadIdx.x * 32] = 0u;
        g_hc[threadIdx.x * 32] = 0u;
    }
}

// ---------------- split x -> xh + xl (bf16) ----------------
__global__ void __launch_bounds__(256) k_splitX(const float* __restrict__ x) {
    size_t i = ((size_t)blockIdx.x * 256 + threadIdx.x) * 4;
    float4 v = *(const float4*)(x + i);
    unsigned short h0 = bfu(v.x), h1 = bfu(v.y), h2 = bfu(v.z), h3 = bfu(v.w);
    unsigned short l0 = bfu(v.x - ubf(h0)), l1 = bfu(v.y - ubf(h1));
    unsigned short l2 = bfu(v.z - ubf(h2)), l3 = bfu(v.w - ubf(h3));
    ull hv = (ull)h0 | ((ull)h1 << 16) | ((ull)h2 << 32) | ((ull)h3 << 48);
    ull lv = (ull)l0 | ((ull)l1 << 16) | ((ull)l2 << 32) | ((ull)l3 << 48);
    *(ull*)(g_xh + i) = hv;
    *(ull*)(g_xl + i) = lv;
}

// ---------------- split + transpose W -> Wht/Wlt [n][k] ----------------
__global__ void __launch_bounds__(256) k_splitW(const float* __restrict__ W) {
    __shared__ float tile[32][33];
    const int k0 = blockIdx.y * 32, n0 = blockIdx.x * 32;
    const int tx = threadIdx.x & 31, ty = threadIdx.x >> 5;
#pragma unroll
    for (int j = 0; j < 32; j += 8)
        tile[ty + j][tx] = W[(size_t)(k0 + ty + j) * NG_ + n0 + tx];
    __syncthreads();
#pragma unroll
    for (int j = 0; j < 32; j += 8) {
        float v = tile[tx][ty + j];
        unsigned short h = bfu(v);
        g_Wht[(size_t)(n0 + ty + j) * D_ + k0 + tx] = *(__nv_bfloat16*)&h;
        unsigned short l = bfu(v - ubf(h));
        g_Wlt[(size_t)(n0 + ty + j) * D_ + k0 + tx] = *(__nv_bfloat16*)&l;
    }
}

// ---------------- tensor-core GEMM (unchanged from R10) ----------------
#define GSM_BUF 20480
__global__ void __launch_bounds__(256, 1) k_gemm_mma() {
    extern __shared__ __nv_bfloat16 smb[];
    const int tid = threadIdx.x;
    const int m0 = blockIdx.y * 128, n0 = blockIdx.x * 128;
    const int w = tid >> 5, lane = tid & 31;
    const int wm = (w & 3) * 32, wn = (w >> 2) * 64;
    const int g = lane >> 2, t4 = lane & 3;

    float C[2][8][4];
#pragma unroll
    for (int mi = 0; mi < 2; mi++)
#pragma unroll
        for (int f = 0; f < 8; f++)
#pragma unroll
            for (int e = 0; e < 4; e++) C[mi][f][e] = 0.f;

    const int sr = tid >> 1;
    const int sc = (tid & 1) * 16;

    auto stage = [&](int kc, int buf) {
        __nv_bfloat16* dst = smb + buf * GSM_BUF;
        const size_t ga = (size_t)(m0 + sr) * D_ + kc * 32 + sc;
        const size_t gb = (size_t)(n0 + sr) * D_ + kc * 32 + sc;
        unsigned d0 = sptr(dst + sr * 40 + sc);
        CPA16(d0,              g_xh + ga);
        CPA16(d0 + 16,         g_xh + ga + 8);
        CPA16(d0 + 10240,      g_xl + ga);
        CPA16(d0 + 10240 + 16, g_xl + ga + 8);
        CPA16(d0 + 20480,      g_Wht + gb);
        CPA16(d0 + 20480 + 16, g_Wht + gb + 8);
        CPA16(d0 + 30720,      g_Wlt + gb);
        CPA16(d0 + 30720 + 16, g_Wlt + gb + 8);
    };

    stage(0, 0); CPCOMMIT();

    for (int kc = 0; kc < 32; kc++) {
        if (kc < 31) { stage(kc + 1, (kc + 1) & 1); CPCOMMIT(); }
        if (kc < 31) CPWAIT1(); else CPWAIT0();
        __syncthreads();

        const u32* S  = (const u32*)(smb + (kc & 1) * GSM_BUF);
        const u32* AL = S + 2560;
        const u32* BH = S + 5120;
        const u32* BL = S + 7680;

#pragma unroll
        for (int ks = 0; ks < 2; ks++) {
            const int cb = ks * 8 + t4;
            u32 ah[2][4], al[2][4];
#pragma unroll
            for (int mi = 0; mi < 2; mi++) {
                int r = wm + mi * 16 + g;
                ah[mi][0] = S[r * 20 + cb];
                ah[mi][1] = S[(r + 8) * 20 + cb];
                ah[mi][2] = S[r * 20 + cb + 4];
                ah[mi][3] = S[(r + 8) * 20 + cb + 4];
                al[mi][0] = AL[r * 20 + cb];
                al[mi][1] = AL[(r + 8) * 20 + cb];
                al[mi][2] = AL[r * 20 + cb + 4];
                al[mi][3] = AL[(r + 8) * 20 + cb + 4];
            }
#pragma unroll
            for (int f = 0; f < 8; f++) {
                int n = wn + f * 8 + g;
                u32 bh0 = BH[n * 20 + cb], bh1 = BH[n * 20 + cb + 4];
                u32 bl0 = BL[n * 20 + cb], bl1 = BL[n * 20 + cb + 4];
#pragma unroll
                for (int mi = 0; mi < 2; mi++) {
                    MMA16816(C[mi][f], ah[mi], bh0, bh1);
                    MMA16816(C[mi][f], al[mi], bh0, bh1);
                    MMA16816(C[mi][f], ah[mi], bl0, bl1);
                }
            }
        }
        __syncthreads();
    }

#pragma unroll
    for (int mi = 0; mi < 2; mi++) {
#pragma unroll
        for (int f = 0; f < 8; f++) {
            int r = m0 + wm + mi * 16 + g;
            int c = n0 + wn + f * 8 + t4 * 2;
            float2 v0 = {C[mi][f][0], C[mi][f][1]};
            float2 v1 = {C[mi][f][2], C[mi][f][3]};
            *(float2*)&g_xp[(size_t)r * NG_ + c]       = v0;
            *(float2*)&g_xp[(size_t)(r + 8) * NG_ + c] = v1;
        }
    }
}

// ---------------- transpose xp -> xpt [t][col][b], fold bias ----------------
__global__ void __launch_bounds__(256) k_xpt() {
    __shared__ float tile[128][33];
    const int t = blockIdx.y;
    const int col0 = blockIdx.x * 128;
    const int tid = threadIdx.x;
    const int b = tid & 31;
    const int cg = tid >> 5;
#pragma unroll
    for (int cc = 0; cc < 4; cc++) {
        int c = cg * 16 + cc * 4;
        float4 v = *(const float4*)&g_xp[((size_t)(b * T_ + t)) * NG_ + col0 + c];
        tile[c + 0][b] = v.x;
        tile[c + 1][b] = v.y;
        tile[c + 2][b] = v.z;
        tile[c + 3][b] = v.w;
    }
    __syncthreads();
    const int c = tid >> 1;
    const int half = tid & 1;
    const float bias = g_bsum[col0 + c];
    float* dst = &g_xpt[((size_t)t * NG_ + col0 + c) * B_ + half * 16];
#pragma unroll
    for (int j = 0; j < 4; j++) {
        float4 o;
        o.x = tile[c][half * 16 + j * 4 + 0] + bias;
        o.y = tile[c][half * 16 + j * 4 + 1] + bias;
        o.z = tile[c][half * 16 + j * 4 + 2] + bias;
        o.w = tile[c][half * 16 + j * 4 + 3] + bias;
        *(float4*)&dst[j * 4] = o;
    }
}

// ---------------- persistent GRU: 2 passes, per-chunk polled exchange ----------------
// smem floats: Uzr[1024*16] | Uh[1024*8] | hst 3x4096 | red 8192 | xps 768 | z_s 256 | hown 256
#define SM_UZR  0
#define SM_UH   16384
#define SM_HST  24576
#define SM_RED  36864
#define SM_XPS  45056
#define SM_ZS   45824
#define SM_HOWN 46080
#define SM_FLOATS 46336

__global__ void __launch_bounds__(512, 1) k_gru(const float* __restrict__ U,
                                                float* __restrict__ out) {
    extern __shared__ float sm[];
    float* Uzr  = sm + SM_UZR;          // [k][16]: cols 0-7 z, 8-15 r
    float* Uh   = sm + SM_UH;           // [k][8]
    float* hst  = sm + SM_HST;          // 3 slots of [128k][32b]
    ull*   red  = (ull*)(sm + SM_RED);
    float* xps  = sm + SM_XPS;          // [0:256)=xz [256:512)=xr [512:768)=xh
    float* z_s  = sm + SM_ZS;
    float* hown = sm + SM_HOWN;

    const int bid = blockIdx.x, tid = threadIdx.x;
    const int u0 = bid * 8;
    const int mychunk = bid >> 4;

    // resident U slices
    for (int i = tid; i < 4096; i += 512) {
        int k = i >> 2, q = i & 3;
        int col = (q < 2) ? (u0 + q * 4) : (UN_ + u0 + (q - 2) * 4);
        *(float4*)&Uzr[k * 16 + q * 4] = *(const float4*)&U[(size_t)k * NG_ + col];
    }
    for (int i = tid; i < 2048; i += 512) {
        int k = i >> 1, q = i & 1;
        *(float4*)&Uh[k * 8 + q * 4] =
            *(const float4*)&U[(size_t)k * NG_ + 2 * UN_ + u0 + q * 4];
    }
    if (tid < 256) hown[tid] = g_hT[0][u0 * B_ + tid];
    __syncthreads();

    // pass1 roles: 32 tiles (8bg x 4cg) x 16 k-segs
    const int tl1 = tid & 31;
    const int b41 = (tl1 & 7) * 4;
    const int c41 = (tl1 >> 3) * 4;
    const int sg1 = tid >> 5;
    // pass2 roles: 16 tiles (8bg x 2cg) x 32 k-segs
    const int tl2 = tid & 15;
    const int b42 = (tl2 & 7) * 4;
    const int c42 = (tl2 >> 3) * 4;
    const int sg2 = tid >> 4;

    auto stage = [&](int c, const float* src) {
        float* dbuf = &hst[(c % 3) * 4096];
        CPA16(sptr(&dbuf[tid * 4]), src + c * 4096 + tid * 4);
        CPA16(sptr(&dbuf[(tid + 512) * 4]), src + c * 4096 + (tid + 512) * 4);
    };

    for (int t = 0; t < T_; t++) {
        const float* hsrc = g_hT[t & 1];
        float*       hdst = g_hT[(t + 1) & 1];
        const float* rhr  = g_rhT[t & 1];
        float*       rhw  = g_rhT[t & 1];
        const float* xpt_t = g_xpt + (size_t)t * NG_ * B_;
        const unsigned tgt_h = 16u * (unsigned)t;
        const unsigned tgt_r = 16u * (unsigned)(t + 1);

        // ============ pass 1: z,r = sigmoid(xzr + h@Uzr); rh -> global ============
        if (tid == 0 && t) {
            POLLGE(&g_hc[0], tgt_h);
            POLLGE(&g_hc[32], tgt_h);
            __threadfence();
        }
        __syncthreads();
        stage(0, hsrc);
        if (tid < 64)
            CPA16(sptr(&xps[tid * 4]), xpt_t + (size_t)u0 * B_ + tid * 4);
        else if (tid < 128)
            CPA16(sptr(&xps[tid * 4]), xpt_t + (size_t)(UN_ + u0) * B_ + (tid - 64) * 4);
        CPCOMMIT();
        stage(1, hsrc); CPCOMMIT();

        ull acc[2][4];
#pragma unroll
        for (int p = 0; p < 2; p++)
#pragma unroll
            for (int j = 0; j < 4; j++) acc[p][j] = 0ULL;

        for (int c = 0; c < 8; c++) {
            if (tid == 0 && t && c + 2 < 8) {
                POLLGE(&g_hc[(c + 2) * 32], tgt_h);
                __threadfence();
            }
            if (c < 7) CPWAIT1(); else CPWAIT0();
            __syncthreads();
            if (c + 2 < 8) { stage(c + 2, hsrc); CPCOMMIT(); }
            const float* hb = &hst[(c % 3) * 4096];
            const int kg = c * 128;
#pragma unroll
            for (int kk = 0; kk < 8; kk++) {
                int kl = sg1 * 8 + kk;
                ulonglong2 hp = *(ulonglong2*)&hb[kl * 32 + b41];
                float uv[4];
                *(float4*)uv = *(float4*)&Uzr[(kg + kl) * 16 + c41];
#pragma unroll
                for (int j = 0; j < 4; j++) {
                    ull dj; DUP2(dj, __float_as_uint(uv[j]));
                    FMA2(acc[0][j], hp.x, dj);
                    FMA2(acc[1][j], hp.y, dj);
                }
            }
        }
        __syncthreads();
#pragma unroll
        for (int q = 0; q < 8; q++)
            red[(sg1 * 8 + q) * 32 + tl1] = acc[q >> 2][q & 3];
        __syncthreads();
        if (tid < 256) {
            int tile = tid & 31, q = tid >> 5;
            ull s = red[q * 32 + tile];
#pragma unroll
            for (int sg = 1; sg < 16; sg++) ADD2(s, red[(sg * 8 + q) * 32 + tile]);
            F2U v; v.u = s;
            int p = q >> 2, j = q & 3;
            int b0 = (tile & 7) * 4 + p * 2;
            int cc = (tile >> 3) * 4 + j;
            if (cc < 8) {
                float z0 = 1.f / (1.f + __expf(-(v.f[0] + xps[cc * 32 + b0])));
                float z1 = 1.f / (1.f + __expf(-(v.f[1] + xps[cc * 32 + b0 + 1])));
                *(float2*)&z_s[cc * 32 + b0] = make_float2(z0, z1);
            } else {
                int ul = cc - 8;
                float r0 = 1.f / (1.f + __expf(-(v.f[0] + xps[256 + ul * 32 + b0])));
                float r1 = 1.f / (1.f + __expf(-(v.f[1] + xps[256 + ul * 32 + b0 + 1])));
                float2 rh = make_float2(r0 * hown[ul * 32 + b0], r1 * hown[ul * 32 + b0 + 1]);
                __stcg((float2*)&rhw[(u0 + ul) * B_ + b0], rh);
                __threadfence();
            }
        }
        __syncthreads();
        if (tid == 0) atomicAdd(&g_rc[mychunk * 32], 1u);

        // ============ pass 2: hc = tanh(xh + rh@Uh); hn ============
        if (tid == 0) {
            POLLGE(&g_rc[0], tgt_r);
            POLLGE(&g_rc[32], tgt_r);
            __threadfence();
        }
        __syncthreads();
        stage(0, rhr);
        if (tid < 64)
            CPA16(sptr(&xps[512 + tid * 4]), xpt_t + (size_t)(2 * UN_ + u0) * B_ + tid * 4);
        CPCOMMIT();
        stage(1, rhr); CPCOMMIT();

#pragma unroll
        for (int p = 0; p < 2; p++)
#pragma unroll
            for (int j = 0; j < 4; j++) acc[p][j] = 0ULL;

        for (int c = 0; c < 8; c++) {
            if (tid == 0 && c + 2 < 8) {
                POLLGE(&g_rc[(c + 2) * 32], tgt_r);
                __threadfence();
            }
            if (c < 7) CPWAIT1(); else CPWAIT0();
            __syncthreads();
            if (c + 2 < 8) { stage(c + 2, rhr); CPCOMMIT(); }
            const float* hb = &hst[(c % 3) * 4096];
            const int kg = c * 128;
#pragma unroll
            for (int kk = 0; kk < 4; kk++) {
                int kl = sg2 * 4 + kk;
                ulonglong2 hp = *(ulonglong2*)&hb[kl * 32 + b42];
                float uv[4];
                *(float4*)uv = *(float4*)&Uh[(kg + kl) * 8 + c42];
#pragma unroll
                for (int j = 0; j < 4; j++) {
                    ull dj; DUP2(dj, __float_as_uint(uv[j]));
                    FMA2(acc[0][j], hp.x, dj);
                    FMA2(acc[1][j], hp.y, dj);
                }
            }
        }
        __syncthreads();
#pragma unroll
        for (int q = 0; q < 8; q++)
            red[(sg2 * 8 + q) * 16 + tl2] = acc[q >> 2][q & 3];
        __syncthreads();
        if (tid < 128) {
            int tile = tid & 15, q = tid >> 4;
            ull s = red[q * 16 + tile];
#pragma unroll
            for (int g2 = 1; g2 < 32; g2++) ADD2(s, red[(g2 * 8 + q) * 16 + tile]);
            F2U v; v.u = s;
            int p = q >> 2, j = q & 3;
            int b0 = (tile & 7) * 4 + p * 2;
            int ul = (tile >> 3) * 4 + j;
            int u  = u0 + ul;
            float2 hn;
#pragma unroll
            for (int e = 0; e < 2; e++) {
                float hc = tanhf(v.f[e] + xps[512 + ul * 32 + b0 + e]);
                float z  = z_s[ul * 32 + b0 + e];
                float ho = hown[ul * 32 + b0 + e];
                float h  = z * ho + (1.f - z) * hc;
                ((float*)&hn)[e] = h;
                hown[ul * 32 + b0 + e] = h;
                out[((size_t)(b0 + e) * T_ + t) * UN_ + u] = h;
            }
            __stcg((float2*)&hdst[u * B_ + b0], hn);
            __threadfence();
        }
        __syncthreads();
        if (tid == 0) atomicAdd(&g_hc[mychunk * 32], 1u);
    }

    // final hidden state hT (buffer 0, T even)
    if (bid < 64) {
        if (tid == 0) {
            POLLGE(&g_hc[(bid >> 3) * 32], 16u * (unsigned)T_);
            __threadfence();
        }
        __syncthreads();
        int i = bid * 512 + tid;          // i = u*32 + b
        int u = i >> 5, b = i & 31;
        out[(size_t)M_ * UN_ + (size_t)b * UN_ + u] = __ldcg(&g_hT[0][i]);
    }
}

// ---------------- launcher ----------------
extern "C" void kernel_launch(void* const* d_in, const int* in_sizes, int n_in,
                              void* d_out, int out_size) {
    const float* x  = (const float*)d_in[0];
    const float* W  = (const float*)d_in[1];
    const float* U  = (const float*)d_in[2];
    const float* b  = (const float*)d_in[3];
    const float* h0 = (const float*)d_in[4];
    float* out = (float*)d_out;

    static bool attr_done = false;
    if (!attr_done) {
        cudaFuncSetAttribute(k_gru, cudaFuncAttributeMaxDynamicSharedMemorySize,
                             SM_FLOATS * sizeof(float));
        cudaFuncSetAttribute(k_gemm_mma, cudaFuncAttributeMaxDynamicSharedMemorySize,
                             2 * GSM_BUF * sizeof(__nv_bfloat16));
        attr_done = true;
    }

    k_bsum<<<NG_ / 256, 256>>>(b);
    k_init<<<NBLK, 256>>>(h0);
    k_splitX<<<(int)((size_t)M_ * D_ / 4 / 256), 256>>>(x);
    {
        dim3 grid(NG_ / 32, D_ / 32);
        k_splitW<<<grid, 256>>>(W);
    }
    {
        dim3 grid(NG_ / 128, M_ / 128);
        k_gemm_mma<<<grid, 256, 2 * GSM_BUF * sizeof(__nv_bfloat16)>>>();
    }
    {
        dim3 grid(NG_ / 128, T_);
        k_xpt<<<grid, 256>>>();
    }
    k_gru<<<NBLK, 512, SM_FLOATS * sizeof(float)>>>(U, out);
}

// round 12
// speedup vs baseline: 1.5031x; 1.5031x over previous
#include <cuda_runtime.h>
#include <cuda_bf16.h>
#include <math.h>

#define B_  32
#define T_  512
#define D_  1024
#define UN_ 1024
#define NG_ 3072
#define M_  (B_*T_)
#define NBLK 128

typedef unsigned long long ull;
typedef unsigned int u32;

// ---------------- packed f32x2 helpers ----------------
#define FMA2(d, a, b) asm("fma.rn.f32x2 %0, %1, %2, %0;" : "+l"(d) : "l"(a), "l"(b))
#define ADD2(d, v)    asm("add.rn.f32x2 %0, %0, %1;"     : "+l"(d) : "l"(v))
#define DUP2(d, s)    asm("mov.b64 %0, {%1, %1};"        : "=l"(d) : "r"(s))

union F2U { ull u; float f[2]; };

// ---------------- cp.async helpers ----------------
__device__ __forceinline__ unsigned sptr(const void* p) {
    return (unsigned)__cvta_generic_to_shared(p);
}
#define CPA16(s, g)  asm volatile("cp.async.cg.shared.global [%0], [%1], 16;" :: "r"(s), "l"(g))
#define CPCOMMIT()   asm volatile("cp.async.commit_group;")
#define CPWAIT2()    asm volatile("cp.async.wait_group 2;")
#define CPWAIT1()    asm volatile("cp.async.wait_group 1;")
#define CPWAIT0()    asm volatile("cp.async.wait_group 0;")

// ---------------- bf16 helpers ----------------
__device__ __forceinline__ unsigned short bfu(float v) {
    __nv_bfloat16 b = __float2bfloat16(v);
    return *(unsigned short*)&b;
}
__device__ __forceinline__ float ubf(unsigned short u) {
    return __bfloat162float(*(__nv_bfloat16*)&u);
}

// ---------------- mma.sync bf16 ----------------
#define MMA16816(c, a, b0, b1)                                              \
    asm("mma.sync.aligned.m16n8k16.row.col.f32.bf16.bf16.f32 "              \
        "{%0,%1,%2,%3}, {%4,%5,%6,%7}, {%8,%9}, {%0,%1,%2,%3};"             \
        : "+f"((c)[0]), "+f"((c)[1]), "+f"((c)[2]), "+f"((c)[3])            \
        : "r"((a)[0]), "r"((a)[1]), "r"((a)[2]), "r"((a)[3]),               \
          "r"(b0), "r"(b1))

// ---------------- device scratch ----------------
__device__ __align__(16) float g_xp[(size_t)M_ * NG_];        // [row][col]
__device__ __align__(16) float g_xpt[(size_t)T_ * NG_ * B_];  // [t][col][b], bias folded
__device__ __align__(16) float g_bsum[NG_];
__device__ __align__(16) float g_hT[2][UN_ * B_];             // [u][b]
__device__ __align__(16) float g_rhT[UN_ * B_];               // [u][b]
__device__ __align__(128) unsigned g_s;
// bf16 split operands
__device__ __align__(16) __nv_bfloat16 g_xh[(size_t)M_ * D_];
__device__ __align__(16) __nv_bfloat16 g_xl[(size_t)M_ * D_];
__device__ __align__(16) __nv_bfloat16 g_Wht[(size_t)NG_ * D_];  // [n][k]
__device__ __align__(16) __nv_bfloat16 g_Wlt[(size_t)NG_ * D_];  // [n][k]

// ---------------- bias column sums ----------------
__global__ void k_bsum(const float* __restrict__ b) {
    int c = blockIdx.x * 256 + threadIdx.x;
    float acc = 0.f;
    for (int k = 0; k < D_; k++) acc += b[(size_t)k * NG_ + c];
    g_bsum[c] = acc;
}

// ---------------- init ----------------
__global__ void k_init(const float* __restrict__ h0) {
    int i = blockIdx.x * 256 + threadIdx.x;
    if (i < B_ * UN_) {
        int u = i >> 5, b = i & 31;
        g_hT[0][i] = h0[b * UN_ + u];
    }
    if (blockIdx.x == 0 && threadIdx.x == 0) g_s = 0u;
}

// ---------------- split x -> xh + xl (bf16) ----------------
__global__ void __launch_bounds__(256) k_splitX(const float* __restrict__ x) {
    size_t i = ((size_t)blockIdx.x * 256 + threadIdx.x) * 4;
    float4 v = *(const float4*)(x + i);
    unsigned short h0 = bfu(v.x), h1 = bfu(v.y), h2 = bfu(v.z), h3 = bfu(v.w);
    unsigned short l0 = bfu(v.x - ubf(h0)), l1 = bfu(v.y - ubf(h1));
    unsigned short l2 = bfu(v.z - ubf(h2)), l3 = bfu(v.w - ubf(h3));
    ull hv = (ull)h0 | ((ull)h1 << 16) | ((ull)h2 << 32) | ((ull)h3 << 48);
    ull lv = (ull)l0 | ((ull)l1 << 16) | ((ull)l2 << 32) | ((ull)l3 << 48);
    *(ull*)(g_xh + i) = hv;
    *(ull*)(g_xl + i) = lv;
}

// ---------------- split + transpose W -> Wht/Wlt [n][k] ----------------
__global__ void __launch_bounds__(256) k_splitW(const float* __restrict__ W) {
    __shared__ float tile[32][33];
    const int k0 = blockIdx.y * 32, n0 = blockIdx.x * 32;
    const int tx = threadIdx.x & 31, ty = threadIdx.x >> 5;
#pragma unroll
    for (int j = 0; j < 32; j += 8)
        tile[ty + j][tx] = W[(size_t)(k0 + ty + j) * NG_ + n0 + tx];
    __syncthreads();
#pragma unroll
    for (int j = 0; j < 32; j += 8) {
        float v = tile[tx][ty + j];
        unsigned short h = bfu(v);
        g_Wht[(size_t)(n0 + ty + j) * D_ + k0 + tx] = *(__nv_bfloat16*)&h;
        unsigned short l = bfu(v - ubf(h));
        g_Wlt[(size_t)(n0 + ty + j) * D_ + k0 + tx] = *(__nv_bfloat16*)&l;
    }
}

// ---------------- tensor-core GEMM (unchanged from R10) ----------------
#define GSM_BUF 20480
__global__ void __launch_bounds__(256, 1) k_gemm_mma() {
    extern __shared__ __nv_bfloat16 smb[];
    const int tid = threadIdx.x;
    const int m0 = blockIdx.y * 128, n0 = blockIdx.x * 128;
    const int w = tid >> 5, lane = tid & 31;
    const int wm = (w & 3) * 32, wn = (w >> 2) * 64;
    const int g = lane >> 2, t4 = lane & 3;

    float C[2][8][4];
#pragma unroll
    for (int mi = 0; mi < 2; mi++)
#pragma unroll
        for (int f = 0; f < 8; f++)
#pragma unroll
            for (int e = 0; e < 4; e++) C[mi][f][e] = 0.f;

    const int sr = tid >> 1;
    const int sc = (tid & 1) * 16;

    auto stage = [&](int kc, int buf) {
        __nv_bfloat16* dst = smb + buf * GSM_BUF;
        const size_t ga = (size_t)(m0 + sr) * D_ + kc * 32 + sc;
        const size_t gb = (size_t)(n0 + sr) * D_ + kc * 32 + sc;
        unsigned d0 = sptr(dst + sr * 40 + sc);
        CPA16(d0,              g_xh + ga);
        CPA16(d0 + 16,         g_xh + ga + 8);
        CPA16(d0 + 10240,      g_xl + ga);
        CPA16(d0 + 10240 + 16, g_xl + ga + 8);
        CPA16(d0 + 20480,      g_Wht + gb);
        CPA16(d0 + 20480 + 16, g_Wht + gb + 8);
        CPA16(d0 + 30720,      g_Wlt + gb);
        CPA16(d0 + 30720 + 16, g_Wlt + gb + 8);
    };

    stage(0, 0); CPCOMMIT();

    for (int kc = 0; kc < 32; kc++) {
        if (kc < 31) { stage(kc + 1, (kc + 1) & 1); CPCOMMIT(); }
        if (kc < 31) CPWAIT1(); else CPWAIT0();
        __syncthreads();

        const u32* S  = (const u32*)(smb + (kc & 1) * GSM_BUF);
        const u32* AL = S + 2560;
        const u32* BH = S + 5120;
        const u32* BL = S + 7680;

#pragma unroll
        for (int ks = 0; ks < 2; ks++) {
            const int cb = ks * 8 + t4;
            u32 ah[2][4], al[2][4];
#pragma unroll
            for (int mi = 0; mi < 2; mi++) {
                int r = wm + mi * 16 + g;
                ah[mi][0] = S[r * 20 + cb];
                ah[mi][1] = S[(r + 8) * 20 + cb];
                ah[mi][2] = S[r * 20 + cb + 4];
                ah[mi][3] = S[(r + 8) * 20 + cb + 4];
                al[mi][0] = AL[r * 20 + cb];
                al[mi][1] = AL[(r + 8) * 20 + cb];
                al[mi][2] = AL[r * 20 + cb + 4];
                al[mi][3] = AL[(r + 8) * 20 + cb + 4];
            }
#pragma unroll
            for (int f = 0; f < 8; f++) {
                int n = wn + f * 8 + g;
                u32 bh0 = BH[n * 20 + cb], bh1 = BH[n * 20 + cb + 4];
                u32 bl0 = BL[n * 20 + cb], bl1 = BL[n * 20 + cb + 4];
#pragma unroll
                for (int mi = 0; mi < 2; mi++) {
                    MMA16816(C[mi][f], ah[mi], bh0, bh1);
                    MMA16816(C[mi][f], al[mi], bh0, bh1);
                    MMA16816(C[mi][f], ah[mi], bl0, bl1);
                }
            }
        }
        __syncthreads();
    }

#pragma unroll
    for (int mi = 0; mi < 2; mi++) {
#pragma unroll
        for (int f = 0; f < 8; f++) {
            int r = m0 + wm + mi * 16 + g;
            int c = n0 + wn + f * 8 + t4 * 2;
            float2 v0 = {C[mi][f][0], C[mi][f][1]};
            float2 v1 = {C[mi][f][2], C[mi][f][3]};
            *(float2*)&g_xp[(size_t)r * NG_ + c]       = v0;
            *(float2*)&g_xp[(size_t)(r + 8) * NG_ + c] = v1;
        }
    }
}

// ---------------- transpose xp -> xpt [t][col][b], fold bias ----------------
__global__ void __launch_bounds__(256) k_xpt() {
    __shared__ float tile[128][33];
    const int t = blockIdx.y;
    const int col0 = blockIdx.x * 128;
    const int tid = threadIdx.x;
    const int b = tid & 31;
    const int cg = tid >> 5;
#pragma unroll
    for (int cc = 0; cc < 4; cc++) {
        int c = cg * 16 + cc * 4;
        float4 v = *(const float4*)&g_xp[((size_t)(b * T_ + t)) * NG_ + col0 + c];
        tile[c + 0][b] = v.x;
        tile[c + 1][b] = v.y;
        tile[c + 2][b] = v.z;
        tile[c + 3][b] = v.w;
    }
    __syncthreads();
    const int c = tid >> 1;
    const int half = tid & 1;
    const float bias = g_bsum[col0 + c];
    float* dst = &g_xpt[((size_t)t * NG_ + col0 + c) * B_ + half * 16];
#pragma unroll
    for (int j = 0; j < 4; j++) {
        float4 o;
        o.x = tile[c][half * 16 + j * 4 + 0] + bias;
        o.y = tile[c][half * 16 + j * 4 + 1] + bias;
        o.z = tile[c][half * 16 + j * 4 + 2] + bias;
        o.w = tile[c][half * 16 + j * 4 + 3] + bias;
        *(float4*)&dst[j * 4] = o;
    }
}

// ---------------- split sync: arrive then (later) wait ----------------
__device__ __forceinline__ void g_arrive() {
    __syncthreads();
    if (threadIdx.x == 0) atomicAdd(&g_s, 1u);
}
__device__ __forceinline__ void g_wait(unsigned tgt) {
    if (threadIdx.x == 0) {
        while (*((volatile unsigned*)&g_s) < tgt) { }
        __threadfence();
    }
    __syncthreads();
}

// ---------------- persistent GRU (R10 skeleton, 2-chunk groups) ----------------
// smem floats: Uz[8192] | Ur[8192] | Uh[8192] | hst 4x4096 | red 8192 | xps 768 | z_s 256 | hown 256
#define SM_UZ   0
#define SM_UR   8192
#define SM_UH   16384
#define SM_HST  24576
#define SM_RED  40960
#define SM_XPS  49152
#define SM_ZS   49920
#define SM_HOWN 50176
#define SM_FLOATS 50432

__global__ void __launch_bounds__(512, 1) k_gru(const float* __restrict__ U,
                                                float* __restrict__ out) {
    extern __shared__ float sm[];
    float* Uz   = sm + SM_UZ;
    float* Ur   = sm + SM_UR;
    float* Uh   = sm + SM_UH;
    float* hst  = sm + SM_HST;          // 4 slots of [128k][32b]
    ull*   red  = (ull*)(sm + SM_RED);
    float* xps  = sm + SM_XPS;          // [0:256)=xz [256:512)=xr [512:768)=xh
    float* z_s  = sm + SM_ZS;
    float* hown = sm + SM_HOWN;

    const int bid = blockIdx.x, tid = threadIdx.x;
    const int u0 = bid * 8;

    for (int i = tid; i < 2048; i += 512) {
        int k = i >> 1, q = i & 1;
        *(float4*)&Uz[k * 8 + q * 4] = *(const float4*)&U[(size_t)k * NG_ + u0 + q * 4];
        *(float4*)&Ur[k * 8 + q * 4] = *(const float4*)&U[(size_t)k * NG_ + UN_ + u0 + q * 4];
        *(float4*)&Uh[k * 8 + q * 4] = *(const float4*)&U[(size_t)k * NG_ + 2 * UN_ + u0 + q * 4];
    }
    if (tid < 256) hown[tid] = g_hT[0][u0 * B_ + tid];
    __syncthreads();

    // roles: 16 tiles (8 bg x 2 cg) x 32 k-segments
    const int tl = tid & 15;
    const int b4 = (tl & 7) * 4;
    const int c4 = (tl >> 3) * 4;
    const int sg = tid >> 4;

    auto stage = [&](int c, const float* src) {
        float* dbuf = &hst[(c & 3) * 4096];
        CPA16(sptr(&dbuf[tid * 4]), src + c * 4096 + tid * 4);
        CPA16(sptr(&dbuf[(tid + 512) * 4]), src + c * 4096 + (tid + 512) * 4);
    };

    // one pass = mainloop over 4 groups of 2 chunks; Um = resident U slice
    // prologue must have staged chunks 0-3 (4 commit groups, chunk0's group may
    // also carry xps loads).
#define PASS_LOOP(Um, src, accv)                                             \
    for (int gq = 0; gq < 4; gq++) {                                         \
        if (gq == 0) CPWAIT2(); else CPWAIT0();                              \
        __syncthreads();                                                     \
        if (gq == 1) { stage(4, src); CPCOMMIT(); stage(5, src); CPCOMMIT(); } \
        else if (gq == 2) { stage(6, src); CPCOMMIT(); stage(7, src); CPCOMMIT(); } \
        _Pragma("unroll")                                                    \
        for (int cc = 0; cc < 2; cc++) {                                     \
            const int c = gq * 2 + cc;                                       \
            const float* hb = &hst[(c & 3) * 4096];                          \
            const int kg = c * 128;                                          \
            _Pragma("unroll")                                                \
            for (int kk = 0; kk < 4; kk++) {                                 \
                int kl = sg * 4 + kk;                                        \
                ulonglong2 hp = *(ulonglong2*)&hb[kl * 32 + b4];             \
                float uv[4];                                                 \
                *(float4*)uv = *(float4*)&Um[(kg + kl) * 8 + c4];            \
                _Pragma("unroll")                                            \
                for (int j = 0; j < 4; j++) {                                \
                    ull dj; DUP2(dj, __float_as_uint(uv[j]));                \
                    FMA2(accv[0][j], hp.x, dj);                              \
                    FMA2(accv[1][j], hp.y, dj);                              \
                }                                                            \
            }                                                                \
        }                                                                    \
    }

    for (int t = 0; t < T_; t++) {
        const float* hsrc = g_hT[t & 1];
        float*       hdst = g_hT[(t + 1) & 1];
        const float* xpt_t = g_xpt + (size_t)t * NG_ * B_;

        // ========== pass 1: r -> rh (global) ==========
        stage(0, hsrc);
        if (tid < 64)
            CPA16(sptr(&xps[tid * 4]), xpt_t + (size_t)u0 * B_ + tid * 4);
        else if (tid < 128)
            CPA16(sptr(&xps[tid * 4]), xpt_t + (size_t)(UN_ + u0) * B_ + (tid - 64) * 4);
        CPCOMMIT();
        stage(1, hsrc); CPCOMMIT();
        stage(2, hsrc); CPCOMMIT();
        stage(3, hsrc); CPCOMMIT();

        ull acc[2][4];
#pragma unroll
        for (int p = 0; p < 2; p++)
#pragma unroll
            for (int j = 0; j < 4; j++) acc[p][j] = 0ULL;

        PASS_LOOP(Ur, hsrc, acc)

        __syncthreads();
#pragma unroll
        for (int q = 0; q < 8; q++)
            red[(sg * 8 + q) * 16 + tl] = acc[q >> 2][q & 3];
        __syncthreads();
        if (tid < 128) {
            int tile = tid & 15, q = tid >> 4;
            ull s = red[q * 16 + tile];
#pragma unroll
            for (int g2 = 1; g2 < 32; g2++) ADD2(s, red[(g2 * 8 + q) * 16 + tile]);
            F2U v; v.u = s;
            int p = q >> 2, j = q & 3;
            int b0 = (tile & 7) * 4 + p * 2;
            int ul = (tile >> 3) * 4 + j;
            float r0 = 1.f / (1.f + __expf(-(v.f[0] + xps[256 + ul * 32 + b0])));
            float r1 = 1.f / (1.f + __expf(-(v.f[1] + xps[256 + ul * 32 + b0 + 1])));
            float2 rh = make_float2(r0 * hown[ul * 32 + b0], r1 * hown[ul * 32 + b0 + 1]);
            __stcg((float2*)&g_rhT[(u0 + ul) * B_ + b0], rh);
            __threadfence();
        }
        g_arrive();   // s1

        // ========== pass 2: z (local) — overlaps barrier wait ==========
        stage(0, hsrc); CPCOMMIT();
        stage(1, hsrc); CPCOMMIT();
        stage(2, hsrc); CPCOMMIT();
        stage(3, hsrc); CPCOMMIT();
#pragma unroll
        for (int p = 0; p < 2; p++)
#pragma unroll
            for (int j = 0; j < 4; j++) acc[p][j] = 0ULL;

        PASS_LOOP(Uz, hsrc, acc)

        __syncthreads();
#pragma unroll
        for (int q = 0; q < 8; q++)
            red[(sg * 8 + q) * 16 + tl] = acc[q >> 2][q & 3];
        __syncthreads();
        if (tid < 128) {
            int tile = tid & 15, q = tid >> 4;
            ull s = red[q * 16 + tile];
#pragma unroll
            for (int g2 = 1; g2 < 32; g2++) ADD2(s, red[(g2 * 8 + q) * 16 + tile]);
            F2U v; v.u = s;
            int p = q >> 2, j = q & 3;
            int b0 = (tile & 7) * 4 + p * 2;
            int ul = (tile >> 3) * 4 + j;
            float z0 = 1.f / (1.f + __expf(-(v.f[0] + xps[ul * 32 + b0])));
            float z1 = 1.f / (1.f + __expf(-(v.f[1] + xps[ul * 32 + b0 + 1])));
            *(float2*)&z_s[ul * 32 + b0] = make_float2(z0, z1);
        }
        g_wait((unsigned)NBLK * (2 * t + 1));

        // ========== pass 3: hcand + hn ==========
        stage(0, g_rhT);
        if (tid < 64)
            CPA16(sptr(&xps[512 + tid * 4]), xpt_t + (size_t)(2 * UN_ + u0) * B_ + tid * 4);
        CPCOMMIT();
        stage(1, g_rhT); CPCOMMIT();
        stage(2, g_rhT); CPCOMMIT();
        stage(3, g_rhT); CPCOMMIT();
#pragma unroll
        for (int p = 0; p < 2; p++)
#pragma unroll
            for (int j = 0; j < 4; j++) acc[p][j] = 0ULL;

        PASS_LOOP(Uh, g_rhT, acc)

        __syncthreads();
#pragma unroll
        for (int q = 0; q < 8; q++)
            red[(sg * 8 + q) * 16 + tl] = acc[q >> 2][q & 3];
        __syncthreads();
        if (tid < 128) {
            int tile = tid & 15, q = tid >> 4;
            ull s = red[q * 16 + tile];
#pragma unroll
            for (int g2 = 1; g2 < 32; g2++) ADD2(s, red[(g2 * 8 + q) * 16 + tile]);
            F2U v; v.u = s;
            int p = q >> 2, j = q & 3;
            int b0 = (tile & 7) * 4 + p * 2;
            int ul = (tile >> 3) * 4 + j;
            int u  = u0 + ul;
            float2 hn;
#pragma unroll
            for (int e = 0; e < 2; e++) {
                float hc = tanhf(v.f[e] + xps[512 + ul * 32 + b0 + e]);
                float z  = z_s[ul * 32 + b0 + e];
                float ho = hown[ul * 32 + b0 + e];
                float h  = z * ho + (1.f - z) * hc;
                ((float*)&hn)[e] = h;
                hown[ul * 32 + b0 + e] = h;
                out[((size_t)(b0 + e) * T_ + t) * UN_ + u] = h;
            }
            __stcg((float2*)&hdst[u * B_ + b0], hn);
            __threadfence();
        }
        g_arrive();
        g_wait((unsigned)NBLK * (2 * t + 2));
    }

    if (bid < 64) {
        int i = bid * 512 + tid;
        int u = i >> 5, b = i & 31;
        out[(size_t)M_ * UN_ + (size_t)b * UN_ + u] = __ldcg(&g_hT[0][i]);
    }
#undef PASS_LOOP
}

// ---------------- launcher ----------------
extern "C" void kernel_launch(void* const* d_in, const int* in_sizes, int n_in,
                              void* d_out, int out_size) {
    const float* x  = (const float*)d_in[0];
    const float* W  = (const float*)d_in[1];
    const float* U  = (const float*)d_in[2];
    const float* b  = (const float*)d_in[3];
    const float* h0 = (const float*)d_in[4];
    float* out = (float*)d_out;

    static bool attr_done = false;
    if (!attr_done) {
        cudaFuncSetAttribute(k_gru, cudaFuncAttributeMaxDynamicSharedMemorySize,
                             SM_FLOATS * sizeof(float));
        cudaFuncSetAttribute(k_gemm_mma, cudaFuncAttributeMaxDynamicSharedMemorySize,
                             2 * GSM_BUF * sizeof(__nv_bfloat16));
        attr_done = true;
    }

    k_bsum<<<NG_ / 256, 256>>>(b);
    k_init<<<NBLK, 256>>>(h0);
    k_splitX<<<(int)((size_t)M_ * D_ / 4 / 256), 256>>>(x);
    {
        dim3 grid(NG_ / 32, D_ / 32);
        k_splitW<<<grid, 256>>>(W);
    }
    {
        dim3 grid(NG_ / 128, M_ / 128);
        k_gemm_mma<<<grid, 256, 2 * GSM_BUF * sizeof(__nv_bfloat16)>>>();
    }
    {
        dim3 grid(NG_ / 128, T_);
        k_xpt<<<grid, 256>>>();
    }
    k_gru<<<NBLK, 512, SM_FLOATS * sizeof(float)>>>(U, out);
}

// round 13
// speedup vs baseline: 1.7762x; 1.1817x over previous
#include <cuda_runtime.h>
#include <cuda_bf16.h>
#include <math.h>

#define B_  32
#define T_  512
#define D_  1024
#define UN_ 1024
#define NG_ 3072
#define M_  (B_*T_)
#define NBLK 128

typedef unsigned long long ull;
typedef unsigned int u32;

// ---------------- packed f32x2 helpers ----------------
#define FMA2(d, a, b) asm("fma.rn.f32x2 %0, %1, %2, %0;" : "+l"(d) : "l"(a), "l"(b))
#define ADD2(d, v)    asm("add.rn.f32x2 %0, %0, %1;"     : "+l"(d) : "l"(v))
#define DUP2(d, s)    asm("mov.b64 %0, {%1, %1};"        : "=l"(d) : "r"(s))

union F2U { ull u; float f[2]; };

// ---------------- cp.async helpers ----------------
__device__ __forceinline__ unsigned sptr(const void* p) {
    return (unsigned)__cvta_generic_to_shared(p);
}
#define CPA16(s, g)  asm volatile("cp.async.cg.shared.global [%0], [%1], 16;" :: "r"(s), "l"(g))
#define CPCOMMIT()   asm volatile("cp.async.commit_group;")
#define CPWAIT1()    asm volatile("cp.async.wait_group 1;")
#define CPWAIT0()    asm volatile("cp.async.wait_group 0;")

// ---------------- bf16 helpers ----------------
__device__ __forceinline__ unsigned short bfu(float v) {
    __nv_bfloat16 b = __float2bfloat16(v);
    return *(unsigned short*)&b;
}
__device__ __forceinline__ float ubf(unsigned short u) {
    return __bfloat162float(*(__nv_bfloat16*)&u);
}

// ---------------- mma.sync bf16 ----------------
#define MMA16816(c, a, b0, b1)                                              \
    asm("mma.sync.aligned.m16n8k16.row.col.f32.bf16.bf16.f32 "              \
        "{%0,%1,%2,%3}, {%4,%5,%6,%7}, {%8,%9}, {%0,%1,%2,%3};"             \
        : "+f"((c)[0]), "+f"((c)[1]), "+f"((c)[2]), "+f"((c)[3])            \
        : "r"((a)[0]), "r"((a)[1]), "r"((a)[2]), "r"((a)[3]),               \
          "r"(b0), "r"(b1))

// ---------------- device scratch ----------------
__device__ __align__(16) float g_xp[(size_t)M_ * NG_];        // [row][col]
__device__ __align__(16) float g_xpt[(size_t)T_ * NG_ * B_];  // [t][col][b], bias folded
__device__ __align__(16) float g_bsum[NG_];
__device__ __align__(16) float g_hT[2][UN_ * B_];             // [u][b]
__device__ __align__(16) float g_rhT[UN_ * B_];               // [u][b]
__device__ __align__(128) unsigned g_s;
// bf16 split operands
__device__ __align__(16) __nv_bfloat16 g_xh[(size_t)M_ * D_];
__device__ __align__(16) __nv_bfloat16 g_xl[(size_t)M_ * D_];
__device__ __align__(16) __nv_bfloat16 g_Wht[(size_t)NG_ * D_];  // [n][k]
__device__ __align__(16) __nv_bfloat16 g_Wlt[(size_t)NG_ * D_];  // [n][k]

// ---------------- bias column sums ----------------
__global__ void k_bsum(const float* __restrict__ b) {
    int c = blockIdx.x * 256 + threadIdx.x;
    float acc = 0.f;
    for (int k = 0; k < D_; k++) acc += b[(size_t)k * NG_ + c];
    g_bsum[c] = acc;
}

// ---------------- init ----------------
__global__ void k_init(const float* __restrict__ h0) {
    int i = blockIdx.x * 256 + threadIdx.x;
    if (i < B_ * UN_) {
        int u = i >> 5, b = i & 31;
        g_hT[0][i] = h0[b * UN_ + u];
    }
    if (blockIdx.x == 0 && threadIdx.x == 0) g_s = 0u;
}

// ---------------- split x -> xh + xl (bf16) ----------------
__global__ void __launch_bounds__(256) k_splitX(const float* __restrict__ x) {
    size_t i = ((size_t)blockIdx.x * 256 + threadIdx.x) * 4;
    float4 v = *(const float4*)(x + i);
    unsigned short h0 = bfu(v.x), h1 = bfu(v.y), h2 = bfu(v.z), h3 = bfu(v.w);
    unsigned short l0 = bfu(v.x - ubf(h0)), l1 = bfu(v.y - ubf(h1));
    unsigned short l2 = bfu(v.z - ubf(h2)), l3 = bfu(v.w - ubf(h3));
    ull hv = (ull)h0 | ((ull)h1 << 16) | ((ull)h2 << 32) | ((ull)h3 << 48);
    ull lv = (ull)l0 | ((ull)l1 << 16) | ((ull)l2 << 32) | ((ull)l3 << 48);
    *(ull*)(g_xh + i) = hv;
    *(ull*)(g_xl + i) = lv;
}

// ---------------- split + transpose W -> Wht/Wlt [n][k] ----------------
__global__ void __launch_bounds__(256) k_splitW(const float* __restrict__ W) {
    __shared__ float tile[32][33];
    const int k0 = blockIdx.y * 32, n0 = blockIdx.x * 32;
    const int tx = threadIdx.x & 31, ty = threadIdx.x >> 5;
#pragma unroll
    for (int j = 0; j < 32; j += 8)
        tile[ty + j][tx] = W[(size_t)(k0 + ty + j) * NG_ + n0 + tx];
    __syncthreads();
#pragma unroll
    for (int j = 0; j < 32; j += 8) {
        float v = tile[tx][ty + j];
        unsigned short h = bfu(v);
        g_Wht[(size_t)(n0 + ty + j) * D_ + k0 + tx] = *(__nv_bfloat16*)&h;
        unsigned short l = bfu(v - ubf(h));
        g_Wlt[(size_t)(n0 + ty + j) * D_ + k0 + tx] = *(__nv_bfloat16*)&l;
    }
}

// ---------------- tensor-core GEMM (unchanged from R10) ----------------
#define GSM_BUF 20480
__global__ void __launch_bounds__(256, 1) k_gemm_mma() {
    extern __shared__ __nv_bfloat16 smb[];
    const int tid = threadIdx.x;
    const int m0 = blockIdx.y * 128, n0 = blockIdx.x * 128;
    const int w = tid >> 5, lane = tid & 31;
    const int wm = (w & 3) * 32, wn = (w >> 2) * 64;
    const int g = lane >> 2, t4 = lane & 3;

    float C[2][8][4];
#pragma unroll
    for (int mi = 0; mi < 2; mi++)
#pragma unroll
        for (int f = 0; f < 8; f++)
#pragma unroll
            for (int e = 0; e < 4; e++) C[mi][f][e] = 0.f;

    const int sr = tid >> 1;
    const int sc = (tid & 1) * 16;

    auto stage = [&](int kc, int buf) {
        __nv_bfloat16* dst = smb + buf * GSM_BUF;
        const size_t ga = (size_t)(m0 + sr) * D_ + kc * 32 + sc;
        const size_t gb = (size_t)(n0 + sr) * D_ + kc * 32 + sc;
        unsigned d0 = sptr(dst + sr * 40 + sc);
        CPA16(d0,              g_xh + ga);
        CPA16(d0 + 16,         g_xh + ga + 8);
        CPA16(d0 + 10240,      g_xl + ga);
        CPA16(d0 + 10240 + 16, g_xl + ga + 8);
        CPA16(d0 + 20480,      g_Wht + gb);
        CPA16(d0 + 20480 + 16, g_Wht + gb + 8);
        CPA16(d0 + 30720,      g_Wlt + gb);
        CPA16(d0 + 30720 + 16, g_Wlt + gb + 8);
    };

    stage(0, 0); CPCOMMIT();

    for (int kc = 0; kc < 32; kc++) {
        if (kc < 31) { stage(kc + 1, (kc + 1) & 1); CPCOMMIT(); }
        if (kc < 31) CPWAIT1(); else CPWAIT0();
        __syncthreads();

        const u32* S  = (const u32*)(smb + (kc & 1) * GSM_BUF);
        const u32* AL = S + 2560;
        const u32* BH = S + 5120;
        const u32* BL = S + 7680;

#pragma unroll
        for (int ks = 0; ks < 2; ks++) {
            const int cb = ks * 8 + t4;
            u32 ah[2][4], al[2][4];
#pragma unroll
            for (int mi = 0; mi < 2; mi++) {
                int r = wm + mi * 16 + g;
                ah[mi][0] = S[r * 20 + cb];
                ah[mi][1] = S[(r + 8) * 20 + cb];
                ah[mi][2] = S[r * 20 + cb + 4];
                ah[mi][3] = S[(r + 8) * 20 + cb + 4];
                al[mi][0] = AL[r * 20 + cb];
                al[mi][1] = AL[(r + 8) * 20 + cb];
                al[mi][2] = AL[r * 20 + cb + 4];
                al[mi][3] = AL[(r + 8) * 20 + cb + 4];
            }
#pragma unroll
            for (int f = 0; f < 8; f++) {
                int n = wn + f * 8 + g;
                u32 bh0 = BH[n * 20 + cb], bh1 = BH[n * 20 + cb + 4];
                u32 bl0 = BL[n * 20 + cb], bl1 = BL[n * 20 + cb + 4];
#pragma unroll
                for (int mi = 0; mi < 2; mi++) {
                    MMA16816(C[mi][f], ah[mi], bh0, bh1);
                    MMA16816(C[mi][f], al[mi], bh0, bh1);
                    MMA16816(C[mi][f], ah[mi], bl0, bl1);
                }
            }
        }
        __syncthreads();
    }

#pragma unroll
    for (int mi = 0; mi < 2; mi++) {
#pragma unroll
        for (int f = 0; f < 8; f++) {
            int r = m0 + wm + mi * 16 + g;
            int c = n0 + wn + f * 8 + t4 * 2;
            float2 v0 = {C[mi][f][0], C[mi][f][1]};
            float2 v1 = {C[mi][f][2], C[mi][f][3]};
            *(float2*)&g_xp[(size_t)r * NG_ + c]       = v0;
            *(float2*)&g_xp[(size_t)(r + 8) * NG_ + c] = v1;
        }
    }
}

// ---------------- transpose xp -> xpt [t][col][b], fold bias ----------------
__global__ void __launch_bounds__(256) k_xpt() {
    __shared__ float tile[128][33];
    const int t = blockIdx.y;
    const int col0 = blockIdx.x * 128;
    const int tid = threadIdx.x;
    const int b = tid & 31;
    const int cg = tid >> 5;
#pragma unroll
    for (int cc = 0; cc < 4; cc++) {
        int c = cg * 16 + cc * 4;
        float4 v = *(const float4*)&g_xp[((size_t)(b * T_ + t)) * NG_ + col0 + c];
        tile[c + 0][b] = v.x;
        tile[c + 1][b] = v.y;
        tile[c + 2][b] = v.z;
        tile[c + 3][b] = v.w;
    }
    __syncthreads();
    const int c = tid >> 1;
    const int half = tid & 1;
    const float bias = g_bsum[col0 + c];
    float* dst = &g_xpt[((size_t)t * NG_ + col0 + c) * B_ + half * 16];
#pragma unroll
    for (int j = 0; j < 4; j++) {
        float4 o;
        o.x = tile[c][half * 16 + j * 4 + 0] + bias;
        o.y = tile[c][half * 16 + j * 4 + 1] + bias;
        o.z = tile[c][half * 16 + j * 4 + 2] + bias;
        o.w = tile[c][half * 16 + j * 4 + 3] + bias;
        *(float4*)&dst[j * 4] = o;
    }
}

// ---------------- split sync: arrive then (later) wait ----------------
__device__ __forceinline__ void g_arrive() {
    __syncthreads();
    if (threadIdx.x == 0) atomicAdd(&g_s, 1u);
}
__device__ __forceinline__ void g_wait(unsigned tgt) {
    if (threadIdx.x == 0) {
        while (*((volatile unsigned*)&g_s) < tgt) { }
        __threadfence();
    }
    __syncthreads();
}

// ---------------- persistent GRU (R10 skeleton + staged groups + shfl reduce) ----------------
// smem floats: Uz[8192] | Ur[8192] | Uh[8192] | hst 6x4096=24576 | red 4096 | xps 768 | z_s 256 | hown 256
#define SM_UZ   0
#define SM_UR   8192
#define SM_UH   16384
#define SM_HST  24576
#define SM_RED  49152
#define SM_XPS  53248
#define SM_ZS   54016
#define SM_HOWN 54272
#define SM_FLOATS 54528

__global__ void __launch_bounds__(512, 1) k_gru(const float* __restrict__ U,
                                                float* __restrict__ out) {
    extern __shared__ float sm[];
    float* Uz   = sm + SM_UZ;
    float* Ur   = sm + SM_UR;
    float* Uh   = sm + SM_UH;
    float* hst  = sm + SM_HST;          // 6 slots of [128k][32b]
    ull*   red  = (ull*)(sm + SM_RED);  // 2048 ull: [16 sgp][8 q][16 tl]
    float* xps  = sm + SM_XPS;          // [0:256)=xz [256:512)=xr [512:768)=xh
    float* z_s  = sm + SM_ZS;
    float* hown = sm + SM_HOWN;

    const int bid = blockIdx.x, tid = threadIdx.x;
    const int u0 = bid * 8;

    for (int i = tid; i < 2048; i += 512) {
        int k = i >> 1, q = i & 1;
        *(float4*)&Uz[k * 8 + q * 4] = *(const float4*)&U[(size_t)k * NG_ + u0 + q * 4];
        *(float4*)&Ur[k * 8 + q * 4] = *(const float4*)&U[(size_t)k * NG_ + UN_ + u0 + q * 4];
        *(float4*)&Uh[k * 8 + q * 4] = *(const float4*)&U[(size_t)k * NG_ + 2 * UN_ + u0 + q * 4];
    }
    if (tid < 256) hown[tid] = g_hT[0][u0 * B_ + tid];
    __syncthreads();

    // roles: 16 tiles (8 bg x 2 cg) x 32 k-segments
    const int tl = tid & 15;
    const int b4 = (tl & 7) * 4;
    const int c4 = (tl >> 3) * 4;
    const int sg = tid >> 4;

    auto stage = [&](int c, const float* src) {
        float* dbuf = &hst[(c % 6) * 4096];
        CPA16(sptr(&dbuf[tid * 4]), src + c * 4096 + tid * 4);
        CPA16(sptr(&dbuf[(tid + 512) * 4]), src + c * 4096 + (tid + 512) * 4);
    };

    // one chunk's FMA contribution
#define CHUNK_FMA(Um, cix)                                                   \
    {                                                                        \
        const float* hb = &hst[((cix) % 6) * 4096];                          \
        const int kg = (cix) * 128;                                          \
        _Pragma("unroll")                                                    \
        for (int kk = 0; kk < 4; kk++) {                                     \
            int kl = sg * 4 + kk;                                            \
            ulonglong2 hp = *(ulonglong2*)&hb[kl * 32 + b4];                 \
            float uv[4];                                                     \
            *(float4*)uv = *(float4*)&Um[(kg + kl) * 8 + c4];                \
            _Pragma("unroll")                                                \
            for (int j = 0; j < 4; j++) {                                    \
                ull dj; DUP2(dj, __float_as_uint(uv[j]));                    \
                FMA2(acc[0][j], hp.x, dj);                                   \
                FMA2(acc[1][j], hp.y, dj);                                   \
            }                                                                \
        }                                                                    \
    }

    // shfl-merge seg pairs, write red, sync (red then has 16 sgp rows)
#define MERGE_WRITE_RED()                                                    \
    {                                                                        \
        _Pragma("unroll")                                                    \
        for (int q = 0; q < 8; q++) {                                        \
            ull o = __shfl_down_sync(0xffffffffu, acc[q >> 2][q & 3], 16);   \
            ADD2(acc[q >> 2][q & 3], o);                                     \
        }                                                                    \
        if ((tid & 16) == 0) {                                               \
            const int sgp = tid >> 5;                                        \
            _Pragma("unroll")                                                \
            for (int q = 0; q < 8; q++)                                      \
                red[(sgp * 8 + q) * 16 + tl] = acc[q >> 2][q & 3];           \
        }                                                                    \
        __syncthreads();                                                     \
    }

    for (int t = 0; t < T_; t++) {
        const float* hsrc = g_hT[t & 1];
        float*       hdst = g_hT[(t + 1) & 1];
        const float* xpt_t = g_xpt + (size_t)t * NG_ * B_;

        ull acc[2][4];

        // ========== pass 1: r -> rh (global) ==========
        stage(0, hsrc);
        stage(1, hsrc);
        if (tid < 64)
            CPA16(sptr(&xps[tid * 4]), xpt_t + (size_t)u0 * B_ + tid * 4);
        else if (tid < 128)
            CPA16(sptr(&xps[tid * 4]), xpt_t + (size_t)(UN_ + u0) * B_ + (tid - 64) * 4);
        CPCOMMIT();                                      // G0: c0,c1,xz,xr
        stage(2, hsrc); stage(3, hsrc); CPCOMMIT();      // G1

#pragma unroll
        for (int p = 0; p < 2; p++)
#pragma unroll
            for (int j = 0; j < 4; j++) acc[p][j] = 0ULL;

        CPWAIT1(); __syncthreads();
        stage(4, hsrc); stage(5, hsrc); CPCOMMIT();      // G2
        CHUNK_FMA(Ur, 0) CHUNK_FMA(Ur, 1)
        CPWAIT1(); __syncthreads();
        stage(6, hsrc); stage(7, hsrc); CPCOMMIT();      // G3 (c6->s0, c7->s1)
        CHUNK_FMA(Ur, 2) CHUNK_FMA(Ur, 3)
        CPWAIT1(); __syncthreads();
        CHUNK_FMA(Ur, 4) CHUNK_FMA(Ur, 5)
        CPWAIT0(); __syncthreads();
        CHUNK_FMA(Ur, 6) CHUNK_FMA(Ur, 7)

        MERGE_WRITE_RED()
        if (tid < 128) {
            int tile = tid & 15, q = tid >> 4;
            ull s = red[q * 16 + tile];
#pragma unroll
            for (int g2 = 1; g2 < 16; g2++) ADD2(s, red[(g2 * 8 + q) * 16 + tile]);
            F2U v; v.u = s;
            int p = q >> 2, j = q & 3;
            int b0 = (tile & 7) * 4 + p * 2;
            int ul = (tile >> 3) * 4 + j;
            float r0 = 1.f / (1.f + __expf(-(v.f[0] + xps[256 + ul * 32 + b0])));
            float r1 = 1.f / (1.f + __expf(-(v.f[1] + xps[256 + ul * 32 + b0 + 1])));
            float2 rh = make_float2(r0 * hown[ul * 32 + b0], r1 * hown[ul * 32 + b0 + 1]);
            __stcg((float2*)&g_rhT[(u0 + ul) * B_ + b0], rh);
            __threadfence();
        }
        g_arrive();   // s1

        // ========== pass 2: z (local) — reuses resident h chunks ==========
        // slots: s0=c6 s1=c7 s2=c2 s3=c3 s4=c4 s5=c5 (from pass 1)
#pragma unroll
        for (int p = 0; p < 2; p++)
#pragma unroll
            for (int j = 0; j < 4; j++) acc[p][j] = 0ULL;

        CHUNK_FMA(Uz, 6) CHUNK_FMA(Uz, 7)
        __syncthreads();                                 // done reading s0,s1
        stage(0, hsrc); stage(1, hsrc); CPCOMMIT();
        CHUNK_FMA(Uz, 2) CHUNK_FMA(Uz, 3) CHUNK_FMA(Uz, 4) CHUNK_FMA(Uz, 5)
        CPWAIT0(); __syncthreads();
        CHUNK_FMA(Uz, 0) CHUNK_FMA(Uz, 1)

        MERGE_WRITE_RED()
        if (tid < 128) {
            int tile = tid & 15, q = tid >> 4;
            ull s = red[q * 16 + tile];
#pragma unroll
            for (int g2 = 1; g2 < 16; g2++) ADD2(s, red[(g2 * 8 + q) * 16 + tile]);
            F2U v; v.u = s;
            int p = q >> 2, j = q & 3;
            int b0 = (tile & 7) * 4 + p * 2;
            int ul = (tile >> 3) * 4 + j;
            float z0 = 1.f / (1.f + __expf(-(v.f[0] + xps[ul * 32 + b0])));
            float z1 = 1.f / (1.f + __expf(-(v.f[1] + xps[ul * 32 + b0 + 1])));
            *(float2*)&z_s[ul * 32 + b0] = make_float2(z0, z1);
        }
        g_wait((unsigned)NBLK * (2 * t + 1));

        // ========== pass 3: hcand + hn ==========
        stage(0, g_rhT);
        stage(1, g_rhT);
        if (tid < 64)
            CPA16(sptr(&xps[512 + tid * 4]), xpt_t + (size_t)(2 * UN_ + u0) * B_ + tid * 4);
        CPCOMMIT();                                      // G0
        stage(2, g_rhT); stage(3, g_rhT); CPCOMMIT();    // G1

#pragma unroll
        for (int p = 0; p < 2; p++)
#pragma unroll
            for (int j = 0; j < 4; j++) acc[p][j] = 0ULL;

        CPWAIT1(); __syncthreads();
        stage(4, g_rhT); stage(5, g_rhT); CPCOMMIT();    // G2
        CHUNK_FMA(Uh, 0) CHUNK_FMA(Uh, 1)
        CPWAIT1(); __syncthreads();
        stage(6, g_rhT); stage(7, g_rhT); CPCOMMIT();    // G3
        CHUNK_FMA(Uh, 2) CHUNK_FMA(Uh, 3)
        CPWAIT1(); __syncthreads();
        CHUNK_FMA(Uh, 4) CHUNK_FMA(Uh, 5)
        CPWAIT0(); __syncthreads();
        CHUNK_FMA(Uh, 6) CHUNK_FMA(Uh, 7)

        MERGE_WRITE_RED()
        if (tid < 128) {
            int tile = tid & 15, q = tid >> 4;
            ull s = red[q * 16 + tile];
#pragma unroll
            for (int g2 = 1; g2 < 16; g2++) ADD2(s, red[(g2 * 8 + q) * 16 + tile]);
            F2U v; v.u = s;
            int p = q >> 2, j = q & 3;
            int b0 = (tile & 7) * 4 + p * 2;
            int ul = (tile >> 3) * 4 + j;
            int u  = u0 + ul;
            float2 hn;
#pragma unroll
            for (int e = 0; e < 2; e++) {
                float hc = tanhf(v.f[e] + xps[512 + ul * 32 + b0 + e]);
                float z  = z_s[ul * 32 + b0 + e];
                float ho = hown[ul * 32 + b0 + e];
                float h  = z * ho + (1.f - z) * hc;
                ((float*)&hn)[e] = h;
                hown[ul * 32 + b0 + e] = h;
                out[((size_t)(b0 + e) * T_ + t) * UN_ + u] = h;
            }
            __stcg((float2*)&hdst[u * B_ + b0], hn);
            __threadfence();
        }
        g_arrive();
        g_wait((unsigned)NBLK * (2 * t + 2));
    }

    if (bid < 64) {
        int i = bid * 512 + tid;
        int u = i >> 5, b = i & 31;
        out[(size_t)M_ * UN_ + (size_t)b * UN_ + u] = __ldcg(&g_hT[0][i]);
    }
#undef CHUNK_FMA
#undef MERGE_WRITE_RED
}

// ---------------- launcher ----------------
extern "C" void kernel_launch(void* const* d_in, const int* in_sizes, int n_in,
                              void* d_out, int out_size) {
    const float* x  = (const float*)d_in[0];
    const float* W  = (const float*)d_in[1];
    const float* U  = (const float*)d_in[2];
    const float* b  = (const float*)d_in[3];
    const float* h0 = (const float*)d_in[4];
    float* out = (float*)d_out;

    static bool attr_done = false;
    if (!attr_done) {
        cudaFuncSetAttribute(k_gru, cudaFuncAttributeMaxDynamicSharedMemorySize,
                             SM_FLOATS * sizeof(float));
        cudaFuncSetAttribute(k_gemm_mma, cudaFuncAttributeMaxDynamicSharedMemorySize,
                             2 * GSM_BUF * sizeof(__nv_bfloat16));
        attr_done = true;
    }

    k_bsum<<<NG_ / 256, 256>>>(b);
    k_init<<<NBLK, 256>>>(h0);
    k_splitX<<<(int)((size_t)M_ * D_ / 4 / 256), 256>>>(x);
    {
        dim3 grid(NG_ / 32, D_ / 32);
        k_splitW<<<grid, 256>>>(W);
    }
    {
        dim3 grid(NG_ / 128, M_ / 128);
        k_gemm_mma<<<grid, 256, 2 * GSM_BUF * sizeof(__nv_bfloat16)>>>();
    }
    {
        dim3 grid(NG_ / 128, T_);
        k_xpt<<<grid, 256>>>();
    }
    k_gru<<<NBLK, 512, SM_FLOATS * sizeof(float)>>>(U, out);
}

// round 14
// speedup vs baseline: 1.7917x; 1.0087x over previous
#include <cuda_runtime.h>
#include <cuda_bf16.h>
#include <math.h>

#define B_  32
#define T_  512
#define D_  1024
#define UN_ 1024
#define NG_ 3072
#define M_  (B_*T_)
#define NBLK 128

typedef unsigned long long ull;
typedef unsigned int u32;

// ---------------- packed f32x2 helpers ----------------
#define FMA2(d, a, b) asm("fma.rn.f32x2 %0, %1, %2, %0;" : "+l"(d) : "l"(a), "l"(b))
#define ADD2(d, v)    asm("add.rn.f32x2 %0, %0, %1;"     : "+l"(d) : "l"(v))
#define DUP2(d, s)    asm("mov.b64 %0, {%1, %1};"        : "=l"(d) : "r"(s))

union F2U { ull u; float f[2]; };

// ---------------- cp.async helpers ----------------
__device__ __forceinline__ unsigned sptr(const void* p) {
    return (unsigned)__cvta_generic_to_shared(p);
}
#define CPA16(s, g)  asm volatile("cp.async.cg.shared.global [%0], [%1], 16;" :: "r"(s), "l"(g))
#define CPCOMMIT()   asm volatile("cp.async.commit_group;")
#define CPWAIT1()    asm volatile("cp.async.wait_group 1;")
#define CPWAIT0()    asm volatile("cp.async.wait_group 0;")

// ---------------- bf16 helpers ----------------
__device__ __forceinline__ unsigned short bfu(float v) {
    __nv_bfloat16 b = __float2bfloat16(v);
    return *(unsigned short*)&b;
}
__device__ __forceinline__ float ubf(unsigned short u) {
    return __bfloat162float(*(__nv_bfloat16*)&u);
}

// ---------------- mma.sync bf16 ----------------
#define MMA16816(c, a, b0, b1)                                              \
    asm("mma.sync.aligned.m16n8k16.row.col.f32.bf16.bf16.f32 "              \
        "{%0,%1,%2,%3}, {%4,%5,%6,%7}, {%8,%9}, {%0,%1,%2,%3};"             \
        : "+f"((c)[0]), "+f"((c)[1]), "+f"((c)[2]), "+f"((c)[3])            \
        : "r"((a)[0]), "r"((a)[1]), "r"((a)[2]), "r"((a)[3]),               \
          "r"(b0), "r"(b1))

// ---------------- device scratch ----------------
__device__ __align__(16) float g_xpt[(size_t)T_ * NG_ * B_];  // [t][col][b], bias folded
__device__ __align__(16) float g_bsum[NG_];
__device__ __align__(16) float g_hT[2][UN_ * B_];             // [u][b]
__device__ __align__(16) float g_rhT[UN_ * B_];               // [u][b]
__device__ __align__(128) unsigned g_s;
// bf16 split operands
__device__ __align__(16) __nv_bfloat16 g_xh[(size_t)M_ * D_];
__device__ __align__(16) __nv_bfloat16 g_xl[(size_t)M_ * D_];
__device__ __align__(16) __nv_bfloat16 g_Wht[(size_t)NG_ * D_];  // [n][k]
__device__ __align__(16) __nv_bfloat16 g_Wlt[(size_t)NG_ * D_];  // [n][k]

// ---------------- bias column sums ----------------
__global__ void k_bsum(const float* __restrict__ b) {
    int c = blockIdx.x * 256 + threadIdx.x;
    float acc = 0.f;
    for (int k = 0; k < D_; k++) acc += b[(size_t)k * NG_ + c];
    g_bsum[c] = acc;
}

// ---------------- init ----------------
__global__ void k_init(const float* __restrict__ h0) {
    int i = blockIdx.x * 256 + threadIdx.x;
    if (i < B_ * UN_) {
        int u = i >> 5, b = i & 31;
        g_hT[0][i] = h0[b * UN_ + u];
    }
    if (blockIdx.x == 0 && threadIdx.x == 0) g_s = 0u;
}

// ---------------- split x -> xh + xl (bf16) ----------------
__global__ void __launch_bounds__(256) k_splitX(const float* __restrict__ x) {
    size_t i = ((size_t)blockIdx.x * 256 + threadIdx.x) * 4;
    float4 v = *(const float4*)(x + i);
    unsigned short h0 = bfu(v.x), h1 = bfu(v.y), h2 = bfu(v.z), h3 = bfu(v.w);
    unsigned short l0 = bfu(v.x - ubf(h0)), l1 = bfu(v.y - ubf(h1));
    unsigned short l2 = bfu(v.z - ubf(h2)), l3 = bfu(v.w - ubf(h3));
    ull hv = (ull)h0 | ((ull)h1 << 16) | ((ull)h2 << 32) | ((ull)h3 << 48);
    ull lv = (ull)l0 | ((ull)l1 << 16) | ((ull)l2 << 32) | ((ull)l3 << 48);
    *(ull*)(g_xh + i) = hv;
    *(ull*)(g_xl + i) = lv;
}

// ---------------- split + transpose W -> Wht/Wlt [n][k] ----------------
__global__ void __launch_bounds__(256) k_splitW(const float* __restrict__ W) {
    __shared__ float tile[32][33];
    const int k0 = blockIdx.y * 32, n0 = blockIdx.x * 32;
    const int tx = threadIdx.x & 31, ty = threadIdx.x >> 5;
#pragma unroll
    for (int j = 0; j < 32; j += 8)
        tile[ty + j][tx] = W[(size_t)(k0 + ty + j) * NG_ + n0 + tx];
    __syncthreads();
#pragma unroll
    for (int j = 0; j < 32; j += 8) {
        float v = tile[tx][ty + j];
        unsigned short h = bfu(v);
        g_Wht[(size_t)(n0 + ty + j) * D_ + k0 + tx] = *(__nv_bfloat16*)&h;
        unsigned short l = bfu(v - ubf(h));
        g_Wlt[(size_t)(n0 + ty + j) * D_ + k0 + tx] = *(__nv_bfloat16*)&l;
    }
}

// ---------------- tensor-core GEMM with fused xpt epilogue ----------------
// M-tile = all 32 b x 4 t (row r = t'*32 + b, t' = r>>5, b = r&31)
// epilogue: C -> smem [r][c] (pad 130) -> coalesced write to g_xpt + bias
#define GSM_BUF 20480
__global__ void __launch_bounds__(256, 1) k_gemm_mma() {
    extern __shared__ __nv_bfloat16 smb[];
    const int tid = threadIdx.x;
    const int t0 = blockIdx.y * 4;
    const int n0 = blockIdx.x * 128;
    const int w = tid >> 5, lane = tid & 31;
    const int wm = (w & 3) * 32, wn = (w >> 2) * 64;
    const int g = lane >> 2, t4 = lane & 3;

    float C[2][8][4];
#pragma unroll
    for (int mi = 0; mi < 2; mi++)
#pragma unroll
        for (int f = 0; f < 8; f++)
#pragma unroll
            for (int e = 0; e < 4; e++) C[mi][f][e] = 0.f;

    const int sr = tid >> 1;
    const int sc = (tid & 1) * 16;
    const int arow = (sr & 31) * T_ + t0 + (sr >> 5);   // b*T + t

    auto stage = [&](int kc, int buf) {
        __nv_bfloat16* dst = smb + buf * GSM_BUF;
        const size_t ga = (size_t)arow * D_ + kc * 32 + sc;
        const size_t gb = (size_t)(n0 + sr) * D_ + kc * 32 + sc;
        unsigned d0 = sptr(dst + sr * 40 + sc);
        CPA16(d0,              g_xh + ga);
        CPA16(d0 + 16,         g_xh + ga + 8);
        CPA16(d0 + 10240,      g_xl + ga);
        CPA16(d0 + 10240 + 16, g_xl + ga + 8);
        CPA16(d0 + 20480,      g_Wht + gb);
        CPA16(d0 + 20480 + 16, g_Wht + gb + 8);
        CPA16(d0 + 30720,      g_Wlt + gb);
        CPA16(d0 + 30720 + 16, g_Wlt + gb + 8);
    };

    stage(0, 0); CPCOMMIT();

    for (int kc = 0; kc < 32; kc++) {
        if (kc < 31) { stage(kc + 1, (kc + 1) & 1); CPCOMMIT(); }
        if (kc < 31) CPWAIT1(); else CPWAIT0();
        __syncthreads();

        const u32* S  = (const u32*)(smb + (kc & 1) * GSM_BUF);
        const u32* AL = S + 2560;
        const u32* BH = S + 5120;
        const u32* BL = S + 7680;

#pragma unroll
        for (int ks = 0; ks < 2; ks++) {
            const int cb = ks * 8 + t4;
            u32 ah[2][4], al[2][4];
#pragma unroll
            for (int mi = 0; mi < 2; mi++) {
                int r = wm + mi * 16 + g;
                ah[mi][0] = S[r * 20 + cb];
                ah[mi][1] = S[(r + 8) * 20 + cb];
                ah[mi][2] = S[r * 20 + cb + 4];
                ah[mi][3] = S[(r + 8) * 20 + cb + 4];
                al[mi][0] = AL[r * 20 + cb];
                al[mi][1] = AL[(r + 8) * 20 + cb];
                al[mi][2] = AL[r * 20 + cb + 4];
                al[mi][3] = AL[(r + 8) * 20 + cb + 4];
            }
#pragma unroll
            for (int f = 0; f < 8; f++) {
                int n = wn + f * 8 + g;
                u32 bh0 = BH[n * 20 + cb], bh1 = BH[n * 20 + cb + 4];
                u32 bl0 = BL[n * 20 + cb], bl1 = BL[n * 20 + cb + 4];
#pragma unroll
                for (int mi = 0; mi < 2; mi++) {
                    MMA16816(C[mi][f], ah[mi], bh0, bh1);
                    MMA16816(C[mi][f], al[mi], bh0, bh1);
                    MMA16816(C[mi][f], ah[mi], bl0, bl1);
                }
            }
        }
        __syncthreads();
    }

    // ---- fused epilogue: C -> smem (pad 130) -> coalesced xpt write + bias ----
    float* sms = (float*)smb;
#pragma unroll
    for (int mi = 0; mi < 2; mi++)
#pragma unroll
        for (int f = 0; f < 8; f++) {
            int r = wm + mi * 16 + g;
            int c = wn + f * 8 + t4 * 2;
            *(float2*)&sms[r * 130 + c]       = make_float2(C[mi][f][0], C[mi][f][1]);
            *(float2*)&sms[(r + 8) * 130 + c] = make_float2(C[mi][f][2], C[mi][f][3]);
        }
    __syncthreads();
    // 16384 output floats; iteration j writes 1024 contiguous (128/warp-instr)
#pragma unroll
    for (int j = 0; j < 16; j++) {
        int L  = j * 1024 + tid * 4;        // = tp*4096 + c*32 + b
        int tp = L >> 12;
        int c  = (L >> 5) & 127;
        int b  = L & 31;
        int r  = tp * 32 + b;
        float bias = g_bsum[n0 + c];
        float4 o;
        o.x = sms[(r + 0) * 130 + c] + bias;
        o.y = sms[(r + 1) * 130 + c] + bias;
        o.z = sms[(r + 2) * 130 + c] + bias;
        o.w = sms[(r + 3) * 130 + c] + bias;
        *(float4*)&g_xpt[((size_t)(t0 + tp) * NG_ + n0 + c) * B_ + b] = o;
    }
}

// ---------------- split sync: arrive then (later) wait ----------------
__device__ __forceinline__ void g_arrive() {
    __syncthreads();
    if (threadIdx.x == 0) atomicAdd(&g_s, 1u);
}
__device__ __forceinline__ void g_wait(unsigned tgt) {
    if (threadIdx.x == 0) {
        while (*((volatile unsigned*)&g_s) < tgt) { }
        __threadfence();
    }
    __syncthreads();
}

// ---------------- persistent GRU (R13, unchanged) ----------------
#define SM_UZ   0
#define SM_UR   8192
#define SM_UH   16384
#define SM_HST  24576
#define SM_RED  49152
#define SM_XPS  53248
#define SM_ZS   54016
#define SM_HOWN 54272
#define SM_FLOATS 54528

__global__ void __launch_bounds__(512, 1) k_gru(const float* __restrict__ U,
                                                float* __restrict__ out) {
    extern __shared__ float sm[];
    float* Uz   = sm + SM_UZ;
    float* Ur   = sm + SM_UR;
    float* Uh   = sm + SM_UH;
    float* hst  = sm + SM_HST;          // 6 slots of [128k][32b]
    ull*   red  = (ull*)(sm + SM_RED);  // 2048 ull
    float* xps  = sm + SM_XPS;
    float* z_s  = sm + SM_ZS;
    float* hown = sm + SM_HOWN;

    const int bid = blockIdx.x, tid = threadIdx.x;
    const int u0 = bid * 8;

    for (int i = tid; i < 2048; i += 512) {
        int k = i >> 1, q = i & 1;
        *(float4*)&Uz[k * 8 + q * 4] = *(const float4*)&U[(size_t)k * NG_ + u0 + q * 4];
        *(float4*)&Ur[k * 8 + q * 4] = *(const float4*)&U[(size_t)k * NG_ + UN_ + u0 + q * 4];
        *(float4*)&Uh[k * 8 + q * 4] = *(const float4*)&U[(size_t)k * NG_ + 2 * UN_ + u0 + q * 4];
    }
    if (tid < 256) hown[tid] = g_hT[0][u0 * B_ + tid];
    __syncthreads();

    const int tl = tid & 15;
    const int b4 = (tl & 7) * 4;
    const int c4 = (tl >> 3) * 4;
    const int sg = tid >> 4;

    auto stage = [&](int c, const float* src) {
        float* dbuf = &hst[(c % 6) * 4096];
        CPA16(sptr(&dbuf[tid * 4]), src + c * 4096 + tid * 4);
        CPA16(sptr(&dbuf[(tid + 512) * 4]), src + c * 4096 + (tid + 512) * 4);
    };

#define CHUNK_FMA(Um, cix)                                                   \
    {                                                                        \
        const float* hb = &hst[((cix) % 6) * 4096];                          \
        const int kg = (cix) * 128;                                          \
        _Pragma("unroll")                                                    \
        for (int kk = 0; kk < 4; kk++) {                                     \
            int kl = sg * 4 + kk;                                            \
            ulonglong2 hp = *(ulonglong2*)&hb[kl * 32 + b4];                 \
            float uv[4];                                                     \
            *(float4*)uv = *(float4*)&Um[(kg + kl) * 8 + c4];                \
            _Pragma("unroll")                                                \
            for (int j = 0; j < 4; j++) {                                    \
                ull dj; DUP2(dj, __float_as_uint(uv[j]));                    \
                FMA2(acc[0][j], hp.x, dj);                                   \
                FMA2(acc[1][j], hp.y, dj);                                   \
            }                                                                \
        }                                                                    \
    }

#define MERGE_WRITE_RED()                                                    \
    {                                                                        \
        _Pragma("unroll")                                                    \
        for (int q = 0; q < 8; q++) {                                        \
            ull o = __shfl_down_sync(0xffffffffu, acc[q >> 2][q & 3], 16);   \
            ADD2(acc[q >> 2][q & 3], o);                                     \
        }                                                                    \
        if ((tid & 16) == 0) {                                               \
            const int sgp = tid >> 5;                                        \
            _Pragma("unroll")                                                \
            for (int q = 0; q < 8; q++)                                      \
                red[(sgp * 8 + q) * 16 + tl] = acc[q >> 2][q & 3];           \
        }                                                                    \
        __syncthreads();                                                     \
    }

    for (int t = 0; t < T_; t++) {
        const float* hsrc = g_hT[t & 1];
        float*       hdst = g_hT[(t + 1) & 1];
        const float* xpt_t = g_xpt + (size_t)t * NG_ * B_;

        ull acc[2][4];

        // ========== pass 1: r -> rh (global) ==========
        stage(0, hsrc);
        stage(1, hsrc);
        if (tid < 64)
            CPA16(sptr(&xps[tid * 4]), xpt_t + (size_t)u0 * B_ + tid * 4);
        else if (tid < 128)
            CPA16(sptr(&xps[tid * 4]), xpt_t + (size_t)(UN_ + u0) * B_ + (tid - 64) * 4);
        CPCOMMIT();                                      // G0
        stage(2, hsrc); stage(3, hsrc); CPCOMMIT();      // G1

#pragma unroll
        for (int p = 0; p < 2; p++)
#pragma unroll
            for (int j = 0; j < 4; j++) acc[p][j] = 0ULL;

        CPWAIT1(); __syncthreads();
        stage(4, hsrc); stage(5, hsrc); CPCOMMIT();      // G2
        CHUNK_FMA(Ur, 0) CHUNK_FMA(Ur, 1)
        CPWAIT1(); __syncthreads();
        stage(6, hsrc); stage(7, hsrc); CPCOMMIT();      // G3
        CHUNK_FMA(Ur, 2) CHUNK_FMA(Ur, 3)
        CPWAIT1(); __syncthreads();
        CHUNK_FMA(Ur, 4) CHUNK_FMA(Ur, 5)
        CPWAIT0(); __syncthreads();
        CHUNK_FMA(Ur, 6) CHUNK_FMA(Ur, 7)

        MERGE_WRITE_RED()
        if (tid < 128) {
            int tile = tid & 15, q = tid >> 4;
            ull s = red[q * 16 + tile];
#pragma unroll
            for (int g2 = 1; g2 < 16; g2++) ADD2(s, red[(g2 * 8 + q) * 16 + tile]);
            F2U v; v.u = s;
            int p = q >> 2, j = q & 3;
            int b0 = (tile & 7) * 4 + p * 2;
            int ul = (tile >> 3) * 4 + j;
            float r0 = 1.f / (1.f + __expf(-(v.f[0] + xps[256 + ul * 32 + b0])));
            float r1 = 1.f / (1.f + __expf(-(v.f[1] + xps[256 + ul * 32 + b0 + 1])));
            float2 rh = make_float2(r0 * hown[ul * 32 + b0], r1 * hown[ul * 32 + b0 + 1]);
            __stcg((float2*)&g_rhT[(u0 + ul) * B_ + b0], rh);
            __threadfence();
        }
        g_arrive();   // s1

        // ========== pass 2: z (local) — reuses resident h chunks ==========
#pragma unroll
        for (int p = 0; p < 2; p++)
#pragma unroll
            for (int j = 0; j < 4; j++) acc[p][j] = 0ULL;

        CHUNK_FMA(Uz, 6) CHUNK_FMA(Uz, 7)
        __syncthreads();
        stage(0, hsrc); stage(1, hsrc); CPCOMMIT();
        CHUNK_FMA(Uz, 2) CHUNK_FMA(Uz, 3) CHUNK_FMA(Uz, 4) CHUNK_FMA(Uz, 5)
        CPWAIT0(); __syncthreads();
        CHUNK_FMA(Uz, 0) CHUNK_FMA(Uz, 1)

        MERGE_WRITE_RED()
        if (tid < 128) {
            int tile = tid & 15, q = tid >> 4;
            ull s = red[q * 16 + tile];
#pragma unroll
            for (int g2 = 1; g2 < 16; g2++) ADD2(s, red[(g2 * 8 + q) * 16 + tile]);
            F2U v; v.u = s;
            int p = q >> 2, j = q & 3;
            int b0 = (tile & 7) * 4 + p * 2;
            int ul = (tile >> 3) * 4 + j;
            float z0 = 1.f / (1.f + __expf(-(v.f[0] + xps[ul * 32 + b0])));
            float z1 = 1.f / (1.f + __expf(-(v.f[1] + xps[ul * 32 + b0 + 1])));
            *(float2*)&z_s[ul * 32 + b0] = make_float2(z0, z1);
        }
        g_wait((unsigned)NBLK * (2 * t + 1));

        // ========== pass 3: hcand + hn ==========
        stage(0, g_rhT);
        stage(1, g_rhT);
        if (tid < 64)
            CPA16(sptr(&xps[512 + tid * 4]), xpt_t + (size_t)(2 * UN_ + u0) * B_ + tid * 4);
        CPCOMMIT();                                      // G0
        stage(2, g_rhT); stage(3, g_rhT); CPCOMMIT();    // G1

#pragma unroll
        for (int p = 0; p < 2; p++)
#pragma unroll
            for (int j = 0; j < 4; j++) acc[p][j] = 0ULL;

        CPWAIT1(); __syncthreads();
        stage(4, g_rhT); stage(5, g_rhT); CPCOMMIT();    // G2
        CHUNK_FMA(Uh, 0) CHUNK_FMA(Uh, 1)
        CPWAIT1(); __syncthreads();
        stage(6, g_rhT); stage(7, g_rhT); CPCOMMIT();    // G3
        CHUNK_FMA(Uh, 2) CHUNK_FMA(Uh, 3)
        CPWAIT1(); __syncthreads();
        CHUNK_FMA(Uh, 4) CHUNK_FMA(Uh, 5)
        CPWAIT0(); __syncthreads();
        CHUNK_FMA(Uh, 6) CHUNK_FMA(Uh, 7)

        MERGE_WRITE_RED()
        if (tid < 128) {
            int tile = tid & 15, q = tid >> 4;
            ull s = red[q * 16 + tile];
#pragma unroll
            for (int g2 = 1; g2 < 16; g2++) ADD2(s, red[(g2 * 8 + q) * 16 + tile]);
            F2U v; v.u = s;
            int p = q >> 2, j = q & 3;
            int b0 = (tile & 7) * 4 + p * 2;
            int ul = (tile >> 3) * 4 + j;
            int u  = u0 + ul;
            float2 hn;
#pragma unroll
            for (int e = 0; e < 2; e++) {
                float hc = tanhf(v.f[e] + xps[512 + ul * 32 + b0 + e]);
                float z  = z_s[ul * 32 + b0 + e];
                float ho = hown[ul * 32 + b0 + e];
                float h  = z * ho + (1.f - z) * hc;
                ((float*)&hn)[e] = h;
                hown[ul * 32 + b0 + e] = h;
                out[((size_t)(b0 + e) * T_ + t) * UN_ + u] = h;
            }
            __stcg((float2*)&hdst[u * B_ + b0], hn);
            __threadfence();
        }
        g_arrive();
        g_wait((unsigned)NBLK * (2 * t + 2));
    }

    if (bid < 64) {
        int i = bid * 512 + tid;
        int u = i >> 5, b = i & 31;
        out[(size_t)M_ * UN_ + (size_t)b * UN_ + u] = __ldcg(&g_hT[0][i]);
    }
#undef CHUNK_FMA
#undef MERGE_WRITE_RED
}

// ---------------- launcher ----------------
extern "C" void kernel_launch(void* const* d_in, const int* in_sizes, int n_in,
                              void* d_out, int out_size) {
    const float* x  = (const float*)d_in[0];
    const float* W  = (const float*)d_in[1];
    const float* U  = (const float*)d_in[2];
    const float* b  = (const float*)d_in[3];
    const float* h0 = (const float*)d_in[4];
    float* out = (float*)d_out;

    static bool attr_done = false;
    if (!attr_done) {
        cudaFuncSetAttribute(k_gru, cudaFuncAttributeMaxDynamicSharedMemorySize,
                             SM_FLOATS * sizeof(float));
        cudaFuncSetAttribute(k_gemm_mma, cudaFuncAttributeMaxDynamicSharedMemorySize,
                             2 * GSM_BUF * sizeof(__nv_bfloat16));
        attr_done = true;
    }

    k_bsum<<<NG_ / 256, 256>>>(b);
    k_init<<<NBLK, 256>>>(h0);
    k_splitX<<<(int)((size_t)M_ * D_ / 4 / 256), 256>>>(x);
    {
        dim3 grid(NG_ / 32, D_ / 32);
        k_splitW<<<grid, 256>>>(W);
    }
    {
        dim3 grid(NG_ / 128, M_ / 128);
        k_gemm_mma<<<grid, 256, 2 * GSM_BUF * sizeof(__nv_bfloat16)>>>();
    }
    k_gru<<<NBLK, 512, SM_FLOATS * sizeof(float)>>>(U, out);
}

// round 15
// speedup vs baseline: 1.7920x; 1.0002x over previous
#include <cuda_runtime.h>
#include <cuda_bf16.h>
#include <math.h>

#define B_  32
#define T_  512
#define D_  1024
#define UN_ 1024
#define NG_ 3072
#define M_  (B_*T_)
#define NBLK 128

typedef unsigned long long ull;
typedef unsigned int u32;

// ---------------- packed f32x2 helpers ----------------
#define FMA2(d, a, b) asm("fma.rn.f32x2 %0, %1, %2, %0;" : "+l"(d) : "l"(a), "l"(b))
#define ADD2(d, v)    asm("add.rn.f32x2 %0, %0, %1;"     : "+l"(d) : "l"(v))
#define DUP2(d, s)    asm("mov.b64 %0, {%1, %1};"        : "=l"(d) : "r"(s))

union F2U { ull u; float f[2]; };

// ---------------- cp.async helpers ----------------
__device__ __forceinline__ unsigned sptr(const void* p) {
    return (unsigned)__cvta_generic_to_shared(p);
}
#define CPA16(s, g)  asm volatile("cp.async.cg.shared.global [%0], [%1], 16;" :: "r"(s), "l"(g))
#define CPCOMMIT()   asm volatile("cp.async.commit_group;")
#define CPWAIT1()    asm volatile("cp.async.wait_group 1;")
#define CPWAIT0()    asm volatile("cp.async.wait_group 0;")

// ---------------- bf16 helpers ----------------
__device__ __forceinline__ unsigned short bfu(float v) {
    __nv_bfloat16 b = __float2bfloat16(v);
    return *(unsigned short*)&b;
}
__device__ __forceinline__ float ubf(unsigned short u) {
    return __bfloat162float(*(__nv_bfloat16*)&u);
}

// ---------------- mma.sync bf16 ----------------
#define MMA16816(c, a, b0, b1)                                              \
    asm("mma.sync.aligned.m16n8k16.row.col.f32.bf16.bf16.f32 "              \
        "{%0,%1,%2,%3}, {%4,%5,%6,%7}, {%8,%9}, {%0,%1,%2,%3};"             \
        : "+f"((c)[0]), "+f"((c)[1]), "+f"((c)[2]), "+f"((c)[3])            \
        : "r"((a)[0]), "r"((a)[1]), "r"((a)[2]), "r"((a)[3]),               \
          "r"(b0), "r"(b1))

// ---------------- device scratch ----------------
__device__ __align__(16) float g_xpt[(size_t)T_ * NG_ * B_];  // [t][col][b], bias folded
__device__ __align__(16) float g_bsum[NG_];
__device__ __align__(16) float g_hT[2][UN_ * B_];             // [u][b]
__device__ __align__(16) float g_rhT[UN_ * B_];               // [u][b]
__device__ __align__(128) unsigned g_s1;
__device__ __align__(128) unsigned g_s2;
// bf16 split operands
__device__ __align__(16) __nv_bfloat16 g_xh[(size_t)M_ * D_];
__device__ __align__(16) __nv_bfloat16 g_xl[(size_t)M_ * D_];
__device__ __align__(16) __nv_bfloat16 g_Wht[(size_t)NG_ * D_];  // [n][k]
__device__ __align__(16) __nv_bfloat16 g_Wlt[(size_t)NG_ * D_];  // [n][k]

// ---------------- prep: bias sums + h0 init + counters (1 launch) ----------------
__global__ void __launch_bounds__(256) k_prep(const float* __restrict__ b,
                                              const float* __restrict__ h0) {
    const int tid = threadIdx.x, bid = blockIdx.x;
    if (bid < 12) {
        int c = bid * 256 + tid;
        float acc = 0.f;
        for (int k = 0; k < D_; k++) acc += b[(size_t)k * NG_ + c];
        g_bsum[c] = acc;
    }
    int i = bid * 256 + tid;            // 0..32767
    int u = i >> 5, bb = i & 31;
    g_hT[0][i] = h0[bb * UN_ + u];
    if (bid == 0 && tid == 0) { g_s1 = 0u; g_s2 = 0u; }
}

// ---------------- split x and W (1 launch) ----------------
__global__ void __launch_bounds__(256) k_split(const float* __restrict__ x,
                                               const float* __restrict__ W) {
    __shared__ float tile[32][33];
    if (blockIdx.x < 16384) {
        size_t i = ((size_t)blockIdx.x * 256 + threadIdx.x) * 4;
        float4 v = *(const float4*)(x + i);
        unsigned short h0 = bfu(v.x), h1 = bfu(v.y), h2 = bfu(v.z), h3 = bfu(v.w);
        unsigned short l0 = bfu(v.x - ubf(h0)), l1 = bfu(v.y - ubf(h1));
        unsigned short l2 = bfu(v.z - ubf(h2)), l3 = bfu(v.w - ubf(h3));
        ull hv = (ull)h0 | ((ull)h1 << 16) | ((ull)h2 << 32) | ((ull)h3 << 48);
        ull lv = (ull)l0 | ((ull)l1 << 16) | ((ull)l2 << 32) | ((ull)l3 << 48);
        *(ull*)(g_xh + i) = hv;
        *(ull*)(g_xl + i) = lv;
    } else {
        int w = blockIdx.x - 16384;          // 0..3071
        const int n0 = (w % 96) * 32;
        const int k0 = (w / 96) * 32;
        const int tx = threadIdx.x & 31, ty = threadIdx.x >> 5;
#pragma unroll
        for (int j = 0; j < 32; j += 8)
            tile[ty + j][tx] = W[(size_t)(k0 + ty + j) * NG_ + n0 + tx];
        __syncthreads();
#pragma unroll
        for (int j = 0; j < 32; j += 8) {
            float v = tile[tx][ty + j];
            unsigned short h = bfu(v);
            g_Wht[(size_t)(n0 + ty + j) * D_ + k0 + tx] = *(__nv_bfloat16*)&h;
            unsigned short l = bfu(v - ubf(h));
            g_Wlt[(size_t)(n0 + ty + j) * D_ + k0 + tx] = *(__nv_bfloat16*)&l;
        }
    }
}

// ---------------- tensor-core GEMM with fused xpt epilogue ----------------
#define GSM_BUF 20480
__global__ void __launch_bounds__(256, 1) k_gemm_mma() {
    extern __shared__ __nv_bfloat16 smb[];
    const int tid = threadIdx.x;
    const int t0 = blockIdx.y * 4;
    const int n0 = blockIdx.x * 128;
    const int w = tid >> 5, lane = tid & 31;
    const int wm = (w & 3) * 32, wn = (w >> 2) * 64;
    const int g = lane >> 2, t4 = lane & 3;

    float C[2][8][4];
#pragma unroll
    for (int mi = 0; mi < 2; mi++)
#pragma unroll
        for (int f = 0; f < 8; f++)
#pragma unroll
            for (int e = 0; e < 4; e++) C[mi][f][e] = 0.f;

    const int sr = tid >> 1;
    const int sc = (tid & 1) * 16;
    const int arow = (sr & 31) * T_ + t0 + (sr >> 5);   // b*T + t

    auto stage = [&](int kc, int buf) {
        __nv_bfloat16* dst = smb + buf * GSM_BUF;
        const size_t ga = (size_t)arow * D_ + kc * 32 + sc;
        const size_t gb = (size_t)(n0 + sr) * D_ + kc * 32 + sc;
        unsigned d0 = sptr(dst + sr * 40 + sc);
        CPA16(d0,              g_xh + ga);
        CPA16(d0 + 16,         g_xh + ga + 8);
        CPA16(d0 + 10240,      g_xl + ga);
        CPA16(d0 + 10240 + 16, g_xl + ga + 8);
        CPA16(d0 + 20480,      g_Wht + gb);
        CPA16(d0 + 20480 + 16, g_Wht + gb + 8);
        CPA16(d0 + 30720,      g_Wlt + gb);
        CPA16(d0 + 30720 + 16, g_Wlt + gb + 8);
    };

    stage(0, 0); CPCOMMIT();

    for (int kc = 0; kc < 32; kc++) {
        if (kc < 31) { stage(kc + 1, (kc + 1) & 1); CPCOMMIT(); }
        if (kc < 31) CPWAIT1(); else CPWAIT0();
        __syncthreads();

        const u32* S  = (const u32*)(smb + (kc & 1) * GSM_BUF);
        const u32* AL = S + 2560;
        const u32* BH = S + 5120;
        const u32* BL = S + 7680;

#pragma unroll
        for (int ks = 0; ks < 2; ks++) {
            const int cb = ks * 8 + t4;
            u32 ah[2][4], al[2][4];
#pragma unroll
            for (int mi = 0; mi < 2; mi++) {
                int r = wm + mi * 16 + g;
                ah[mi][0] = S[r * 20 + cb];
                ah[mi][1] = S[(r + 8) * 20 + cb];
                ah[mi][2] = S[r * 20 + cb + 4];
                ah[mi][3] = S[(r + 8) * 20 + cb + 4];
                al[mi][0] = AL[r * 20 + cb];
                al[mi][1] = AL[(r + 8) * 20 + cb];
                al[mi][2] = AL[r * 20 + cb + 4];
                al[mi][3] = AL[(r + 8) * 20 + cb + 4];
            }
#pragma unroll
            for (int f = 0; f < 8; f++) {
                int n = wn + f * 8 + g;
                u32 bh0 = BH[n * 20 + cb], bh1 = BH[n * 20 + cb + 4];
                u32 bl0 = BL[n * 20 + cb], bl1 = BL[n * 20 + cb + 4];
#pragma unroll
                for (int mi = 0; mi < 2; mi++) {
                    MMA16816(C[mi][f], ah[mi], bh0, bh1);
                    MMA16816(C[mi][f], al[mi], bh0, bh1);
                    MMA16816(C[mi][f], ah[mi], bl0, bl1);
                }
            }
        }
        __syncthreads();
    }

    // ---- fused epilogue: C -> smem (pad 130) -> coalesced xpt write + bias ----
    float* sms = (float*)smb;
#pragma unroll
    for (int mi = 0; mi < 2; mi++)
#pragma unroll
        for (int f = 0; f < 8; f++) {
            int r = wm + mi * 16 + g;
            int c = wn + f * 8 + t4 * 2;
            *(float2*)&sms[r * 130 + c]       = make_float2(C[mi][f][0], C[mi][f][1]);
            *(float2*)&sms[(r + 8) * 130 + c] = make_float2(C[mi][f][2], C[mi][f][3]);
        }
    __syncthreads();
#pragma unroll
    for (int j = 0; j < 16; j++) {
        int L  = j * 1024 + tid * 4;
        int tp = L >> 12;
        int c  = (L >> 5) & 127;
        int b  = L & 31;
        int r  = tp * 32 + b;
        float bias = g_bsum[n0 + c];
        float4 o;
        o.x = sms[(r + 0) * 130 + c] + bias;
        o.y = sms[(r + 1) * 130 + c] + bias;
        o.z = sms[(r + 2) * 130 + c] + bias;
        o.w = sms[(r + 3) * 130 + c] + bias;
        *(float4*)&g_xpt[((size_t)(t0 + tp) * NG_ + n0 + c) * B_ + b] = o;
    }
}

// ---------------- split sync: arrive then (later) wait, backoff poll ----------------
__device__ __forceinline__ void g_arrive(unsigned* cnt) {
    __syncthreads();
    if (threadIdx.x == 0) atomicAdd(cnt, 1u);
}
__device__ __forceinline__ void g_wait(unsigned* cnt, unsigned tgt) {
    if (threadIdx.x == 0) {
        int spins = 0;
        while (*((volatile unsigned*)cnt) < tgt) {
            if (++spins > 8) __nanosleep(64);
        }
        __threadfence();
    }
    __syncthreads();
}

// ---------------- persistent GRU (R13 schedule, unchanged math) ----------------
#define SM_UZ   0
#define SM_UR   8192
#define SM_UH   16384
#define SM_HST  24576
#define SM_RED  49152
#define SM_XPS  53248
#define SM_ZS   54016
#define SM_HOWN 54272
#define SM_FLOATS 54528

__global__ void __launch_bounds__(512, 1) k_gru(const float* __restrict__ U,
                                                float* __restrict__ out) {
    extern __shared__ float sm[];
    float* Uz   = sm + SM_UZ;
    float* Ur   = sm + SM_UR;
    float* Uh   = sm + SM_UH;
    float* hst  = sm + SM_HST;          // 6 slots of [128k][32b]
    ull*   red  = (ull*)(sm + SM_RED);  // 2048 ull
    float* xps  = sm + SM_XPS;
    float* z_s  = sm + SM_ZS;
    float* hown = sm + SM_HOWN;

    const int bid = blockIdx.x, tid = threadIdx.x;
    const int u0 = bid * 8;

    for (int i = tid; i < 2048; i += 512) {
        int k = i >> 1, q = i & 1;
        *(float4*)&Uz[k * 8 + q * 4] = *(const float4*)&U[(size_t)k * NG_ + u0 + q * 4];
        *(float4*)&Ur[k * 8 + q * 4] = *(const float4*)&U[(size_t)k * NG_ + UN_ + u0 + q * 4];
        *(float4*)&Uh[k * 8 + q * 4] = *(const float4*)&U[(size_t)k * NG_ + 2 * UN_ + u0 + q * 4];
    }
    if (tid < 256) hown[tid] = g_hT[0][u0 * B_ + tid];
    __syncthreads();

    const int tl = tid & 15;
    const int b4 = (tl & 7) * 4;
    const int c4 = (tl >> 3) * 4;
    const int sg = tid >> 4;

    auto stage = [&](int c, const float* src) {
        float* dbuf = &hst[(c % 6) * 4096];
        CPA16(sptr(&dbuf[tid * 4]), src + c * 4096 + tid * 4);
        CPA16(sptr(&dbuf[(tid + 512) * 4]), src + c * 4096 + (tid + 512) * 4);
    };

#define CHUNK_FMA(Um, cix)                                                   \
    {                                                                        \
        const float* hb = &hst[((cix) % 6) * 4096];                          \
        const int kg = (cix) * 128;                                          \
        _Pragma("unroll")                                                    \
        for (int kk = 0; kk < 4; kk++) {                                     \
            int kl = sg * 4 + kk;                                            \
            ulonglong2 hp = *(ulonglong2*)&hb[kl * 32 + b4];                 \
            float uv[4];                                                     \
            *(float4*)uv = *(float4*)&Um[(kg + kl) * 8 + c4];                \
            _Pragma("unroll")                                                \
            for (int j = 0; j < 4; j++) {                                    \
                ull dj; DUP2(dj, __float_as_uint(uv[j]));                    \
                FMA2(acc[0][j], hp.x, dj);                                   \
                FMA2(acc[1][j], hp.y, dj);                                   \
            }                                                                \
        }                                                                    \
    }

#define MERGE_WRITE_RED()                                                    \
    {                                                                        \
        _Pragma("unroll")                                                    \
        for (int q = 0; q < 8; q++) {                                        \
            ull o = __shfl_down_sync(0xffffffffu, acc[q >> 2][q & 3], 16);   \
            ADD2(acc[q >> 2][q & 3], o);                                     \
        }                                                                    \
        if ((tid & 16) == 0) {                                               \
            const int sgp = tid >> 5;                                        \
            _Pragma("unroll")                                                \
            for (int q = 0; q < 8; q++)                                      \
                red[(sgp * 8 + q) * 16 + tl] = acc[q >> 2][q & 3];           \
        }                                                                    \
        __syncthreads();                                                     \
    }

    for (int t = 0; t < T_; t++) {
        const float* hsrc = g_hT[t & 1];
        float*       hdst = g_hT[(t + 1) & 1];
        const float* xpt_t = g_xpt + (size_t)t * NG_ * B_;

        ull acc[2][4];

        // ========== pass 1: r -> rh (global) ==========
        stage(0, hsrc);
        stage(1, hsrc);
        if (tid < 64)
            CPA16(sptr(&xps[tid * 4]), xpt_t + (size_t)u0 * B_ + tid * 4);
        else if (tid < 128)
            CPA16(sptr(&xps[tid * 4]), xpt_t + (size_t)(UN_ + u0) * B_ + (tid - 64) * 4);
        CPCOMMIT();                                      // G0
        stage(2, hsrc); stage(3, hsrc); CPCOMMIT();      // G1

#pragma unroll
        for (int p = 0; p < 2; p++)
#pragma unroll
            for (int j = 0; j < 4; j++) acc[p][j] = 0ULL;

        CPWAIT1(); __syncthreads();
        stage(4, hsrc); stage(5, hsrc); CPCOMMIT();      // G2
        CHUNK_FMA(Ur, 0) CHUNK_FMA(Ur, 1)
        CPWAIT1(); __syncthreads();
        stage(6, hsrc); stage(7, hsrc); CPCOMMIT();      // G3
        CHUNK_FMA(Ur, 2) CHUNK_FMA(Ur, 3)
        CPWAIT1(); __syncthreads();
        CHUNK_FMA(Ur, 4) CHUNK_FMA(Ur, 5)
        CPWAIT0(); __syncthreads();
        CHUNK_FMA(Ur, 6) CHUNK_FMA(Ur, 7)

        MERGE_WRITE_RED()
        if (tid < 128) {
            int tile = tid & 15, q = tid >> 4;
            ull s = red[q * 16 + tile];
#pragma unroll
            for (int g2 = 1; g2 < 16; g2++) ADD2(s, red[(g2 * 8 + q) * 16 + tile]);
            F2U v; v.u = s;
            int p = q >> 2, j = q & 3;
            int b0 = (tile & 7) * 4 + p * 2;
            int ul = (tile >> 3) * 4 + j;
            float r0 = 1.f / (1.f + __expf(-(v.f[0] + xps[256 + ul * 32 + b0])));
            float r1 = 1.f / (1.f + __expf(-(v.f[1] + xps[256 + ul * 32 + b0 + 1])));
            float2 rh = make_float2(r0 * hown[ul * 32 + b0], r1 * hown[ul * 32 + b0 + 1]);
            __stcg((float2*)&g_rhT[(u0 + ul) * B_ + b0], rh);
            __threadfence();
        }
        g_arrive(&g_s1);

        // ========== pass 2: z (local) — reuses resident h chunks ==========
#pragma unroll
        for (int p = 0; p < 2; p++)
#pragma unroll
            for (int j = 0; j < 4; j++) acc[p][j] = 0ULL;

        CHUNK_FMA(Uz, 6) CHUNK_FMA(Uz, 7)
        __syncthreads();
        stage(0, hsrc); stage(1, hsrc); CPCOMMIT();
        CHUNK_FMA(Uz, 2) CHUNK_FMA(Uz, 3) CHUNK_FMA(Uz, 4) CHUNK_FMA(Uz, 5)
        CPWAIT0(); __syncthreads();
        CHUNK_FMA(Uz, 0) CHUNK_FMA(Uz, 1)

        MERGE_WRITE_RED()
        if (tid < 128) {
            int tile = tid & 15, q = tid >> 4;
            ull s = red[q * 16 + tile];
#pragma unroll
            for (int g2 = 1; g2 < 16; g2++) ADD2(s, red[(g2 * 8 + q) * 16 + tile]);
            F2U v; v.u = s;
            int p = q >> 2, j = q & 3;
            int b0 = (tile & 7) * 4 + p * 2;
            int ul = (tile >> 3) * 4 + j;
            float z0 = 1.f / (1.f + __expf(-(v.f[0] + xps[ul * 32 + b0])));
            float z1 = 1.f / (1.f + __expf(-(v.f[1] + xps[ul * 32 + b0 + 1])));
            *(float2*)&z_s[ul * 32 + b0] = make_float2(z0, z1);
        }
        g_wait(&g_s1, (unsigned)NBLK * (t + 1));

        // ========== pass 3: hcand + hn ==========
        stage(0, g_rhT);
        stage(1, g_rhT);
        if (tid < 64)
            CPA16(sptr(&xps[512 + tid * 4]), xpt_t + (size_t)(2 * UN_ + u0) * B_ + tid * 4);
        CPCOMMIT();                                      // G0
        stage(2, g_rhT); stage(3, g_rhT); CPCOMMIT();    // G1

#pragma unroll
        for (int p = 0; p < 2; p++)
#pragma unroll
            for (int j = 0; j < 4; j++) acc[p][j] = 0ULL;

        CPWAIT1(); __syncthreads();
        stage(4, g_rhT); stage(5, g_rhT); CPCOMMIT();    // G2
        CHUNK_FMA(Uh, 0) CHUNK_FMA(Uh, 1)
        CPWAIT1(); __syncthreads();
        stage(6, g_rhT); stage(7, g_rhT); CPCOMMIT();    // G3
        CHUNK_FMA(Uh, 2) CHUNK_FMA(Uh, 3)
        CPWAIT1(); __syncthreads();
        CHUNK_FMA(Uh, 4) CHUNK_FMA(Uh, 5)
        CPWAIT0(); __syncthreads();
        CHUNK_FMA(Uh, 6) CHUNK_FMA(Uh, 7)

        MERGE_WRITE_RED()
        if (tid < 128) {
            int tile = tid & 15, q = tid >> 4;
            ull s = red[q * 16 + tile];
#pragma unroll
            for (int g2 = 1; g2 < 16; g2++) ADD2(s, red[(g2 * 8 + q) * 16 + tile]);
            F2U v; v.u = s;
            int p = q >> 2, j = q & 3;
            int b0 = (tile & 7) * 4 + p * 2;
            int ul = (tile >> 3) * 4 + j;
            int u  = u0 + ul;
            float2 hn;
#pragma unroll
            for (int e = 0; e < 2; e++) {
                float hc = tanhf(v.f[e] + xps[512 + ul * 32 + b0 + e]);
                float z  = z_s[ul * 32 + b0 + e];
                float ho = hown[ul * 32 + b0 + e];
                float h  = z * ho + (1.f - z) * hc;
                ((float*)&hn)[e] = h;
                hown[ul * 32 + b0 + e] = h;
                out[((size_t)(b0 + e) * T_ + t) * UN_ + u] = h;
            }
            __stcg((float2*)&hdst[u * B_ + b0], hn);
            __threadfence();
        }
        g_arrive(&g_s2);
        g_wait(&g_s2, (unsigned)NBLK * (t + 1));
    }

    if (bid < 64) {
        int i = bid * 512 + tid;
        int u = i >> 5, b = i & 31;
        out[(size_t)M_ * UN_ + (size_t)b * UN_ + u] = __ldcg(&g_hT[0][i]);
    }
#undef CHUNK_FMA
#undef MERGE_WRITE_RED
}

// ---------------- launcher ----------------
extern "C" void kernel_launch(void* const* d_in, const int* in_sizes, int n_in,
                              void* d_out, int out_size) {
    const float* x  = (const float*)d_in[0];
    const float* W  = (const float*)d_in[1];
    const float* U  = (const float*)d_in[2];
    const float* b  = (const float*)d_in[3];
    const float* h0 = (const float*)d_in[4];
    float* out = (float*)d_out;

    static bool attr_done = false;
    if (!attr_done) {
        cudaFuncSetAttribute(k_gru, cudaFuncAttributeMaxDynamicSharedMemorySize,
                             SM_FLOATS * sizeof(float));
        cudaFuncSetAttribute(k_gemm_mma, cudaFuncAttributeMaxDynamicSharedMemorySize,
                             2 * GSM_BUF * sizeof(__nv_bfloat16));
        attr_done = true;
    }

    k_prep<<<NBLK, 256>>>(b, h0);                       // launch 1
    k_split<<<16384 + 3072, 256>>>(x, W);               // launch 2
    {
        dim3 grid(NG_ / 128, M_ / 128);
        k_gemm_mma<<<grid, 256, 2 * GSM_BUF * sizeof(__nv_bfloat16)>>>();  // launch 3
    }
    k_gru<<<NBLK, 512, SM_FLOATS * sizeof(float)>>>(U, out);               // launch 4
}